// round 9
// baseline (speedup 1.0000x reference)
#include <cuda_runtime.h>
#include <cuda_bf16.h>
#include <math.h>
#include <stdint.h>

#define NUM_SRC   200000
#define NUM_DST   100000
#define NUM_EDGES 1600000
#define IN_DIM    128
#define HID       256
#define OUT_DIM   128
#define NRB       1563      // ceil(NUM_DST/64)
#define BUCKET_CAP 64

// ---------------------------------------------------------------------------
// Scratch (__device__ globals; no allocation allowed)
// ---------------------------------------------------------------------------
__device__ __align__(16) int      g_deg[NUM_DST];                      // 0.4 MB
__device__ __align__(16) int      g_bucket[(size_t)NUM_DST * BUCKET_CAP]; // 25.6 MB
__device__ __align__(16) uint32_t g_ah[(size_t)NUM_DST * 128];         // A=[mean|x] bf16 hi, [row][kp]
__device__ __align__(16) uint32_t g_al[(size_t)NUM_DST * 128];         // A lo
__device__ __align__(16) uint32_t g_hh[(size_t)NUM_DST * 128];         // h bf16 hi, [row][kp]
__device__ __align__(16) uint32_t g_hl[(size_t)NUM_DST * 128];         // h lo
__device__ __align__(16) uint32_t g_wh[256 * 128];                     // W_cat hi  [n][kp]
__device__ __align__(16) uint32_t g_wl[256 * 128];                     // W_cat lo
__device__ __align__(16) uint32_t g_wohi[128 * 128];                   // W_out hi  [n][kp]
__device__ __align__(16) uint32_t g_wolo[128 * 128];                   // W_out lo

// ---------------------------------------------------------------------------
// helpers
// ---------------------------------------------------------------------------
__device__ __forceinline__ uint32_t smem_u32(const void* p) {
    uint32_t a;
    asm("{ .reg .u64 t; cvta.to.shared.u64 t, %1; cvt.u32.u64 %0, t; }" : "=r"(a) : "l"(p));
    return a;
}
__device__ __forceinline__ void split2(float a0, float a1, uint32_t& hi, uint32_t& lo) {
    __nv_bfloat16 h0 = __float2bfloat16(a0), h1 = __float2bfloat16(a1);
    __nv_bfloat16 l0 = __float2bfloat16(a0 - __bfloat162float(h0));
    __nv_bfloat16 l1 = __float2bfloat16(a1 - __bfloat162float(h1));
    __nv_bfloat162 H; H.x = h0; H.y = h1;
    __nv_bfloat162 L; L.x = l0; L.y = l1;
    hi = *(uint32_t*)&H; lo = *(uint32_t*)&L;
}
__device__ __forceinline__ float gelu_exact(float t) {
    return 0.5f * t * (1.0f + erff(t * 0.70710678118654752f));
}

#define MMA(c, A0, A1, A2, A3, B0, B1)                                          \
    asm("mma.sync.aligned.m16n8k16.row.col.f32.bf16.bf16.f32 "                  \
        "{%0,%1,%2,%3},{%4,%5,%6,%7},{%8,%9},{%0,%1,%2,%3};"                    \
        : "+f"((c)[0]), "+f"((c)[1]), "+f"((c)[2]), "+f"((c)[3])                \
        : "r"(A0), "r"(A1), "r"(A2), "r"(A3), "r"(B0), "r"(B1))

#define LDSM4(R, addr)                                                          \
    asm volatile("ldmatrix.sync.aligned.m8n8.x4.shared.b16 {%0,%1,%2,%3}, [%4];"\
        : "=r"((R)[0]), "=r"((R)[1]), "=r"((R)[2]), "=r"((R)[3]) : "r"(addr))

#define CPA(dst, src, sz)                                                       \
    asm volatile("cp.async.ca.shared.global [%0], [%1], 16, %2;"                \
        :: "r"(dst), "l"(src), "r"(sz))
#define CPA16(dst, src)                                                         \
    asm volatile("cp.async.ca.shared.global [%0], [%1], 16;" :: "r"(dst), "l"(src))
#define CPCOMMIT() asm volatile("cp.async.commit_group;" ::: "memory")

// ---------------------------------------------------------------------------
// K0: zero degree counters
// ---------------------------------------------------------------------------
__global__ void zero_deg() {
    int i = blockIdx.x * 256 + threadIdx.x;
    if (i < NUM_DST) g_deg[i] = 0;
}

// ---------------------------------------------------------------------------
// K1: fill buckets — per edge: slot = atomicAdd(deg[dst]), bucket[dst][slot]=src
// ---------------------------------------------------------------------------
__global__ void fill_kernel(const int* __restrict__ esrc,
                            const int* __restrict__ edst) {
    int e = blockIdx.x * 256 + threadIdx.x;
    if (e >= NUM_EDGES) return;
    int s = __ldg(esrc + e);
    int d = __ldg(edst + e);
    int pos = atomicAdd(&g_deg[d], 1);
    if (pos < BUCKET_CAP)
        g_bucket[(size_t)d * BUCKET_CAP + pos] = s;
}

// ---------------------------------------------------------------------------
// K2: aggregate — warp per dst: register-accumulate neighbor mean, then emit
// split-bf16 A = [mean_nbr | x_tgt] straight into g_ah/g_al. No float atomics.
// ---------------------------------------------------------------------------
__global__ void agg_kernel(const float* __restrict__ x) {
    int d    = blockIdx.x * 8 + (threadIdx.x >> 5);
    int lane = threadIdx.x & 31;
    if (d >= NUM_DST) return;

    int degT = g_deg[d];
    int deg  = min(degT, BUCKET_CAP);
    const int* lst = g_bucket + (size_t)d * BUCKET_CAP;
    const float4* x4 = (const float4*)x;

    float4 a0 = make_float4(0.f, 0.f, 0.f, 0.f);
    float4 a1 = make_float4(0.f, 0.f, 0.f, 0.f);
    float4 a2 = make_float4(0.f, 0.f, 0.f, 0.f);
    float4 a3 = make_float4(0.f, 0.f, 0.f, 0.f);

    int i = 0;
    for (; i + 4 <= deg; i += 4) {
        int s0 = __ldg(lst + i),     s1 = __ldg(lst + i + 1);
        int s2 = __ldg(lst + i + 2), s3 = __ldg(lst + i + 3);
        float4 v0 = __ldg(x4 + (size_t)s0 * 32 + lane);
        float4 v1 = __ldg(x4 + (size_t)s1 * 32 + lane);
        float4 v2 = __ldg(x4 + (size_t)s2 * 32 + lane);
        float4 v3 = __ldg(x4 + (size_t)s3 * 32 + lane);
        a0.x += v0.x; a0.y += v0.y; a0.z += v0.z; a0.w += v0.w;
        a1.x += v1.x; a1.y += v1.y; a1.z += v1.z; a1.w += v1.w;
        a2.x += v2.x; a2.y += v2.y; a2.z += v2.z; a2.w += v2.w;
        a3.x += v3.x; a3.y += v3.y; a3.z += v3.z; a3.w += v3.w;
    }
    for (; i < deg; ++i) {
        int s = __ldg(lst + i);
        float4 v = __ldg(x4 + (size_t)s * 32 + lane);
        a0.x += v.x; a0.y += v.y; a0.z += v.z; a0.w += v.w;
    }
    float inv = 1.0f / fmaxf((float)degT, 1.0f);
    float m0 = (a0.x + a1.x + a2.x + a3.x) * inv;
    float m1 = (a0.y + a1.y + a2.y + a3.y) * inv;
    float m2 = (a0.z + a1.z + a2.z + a3.z) * inv;
    float m3 = (a0.w + a1.w + a2.w + a3.w) * inv;

    uint32_t h0, l0, h1, l1;
    split2(m0, m1, h0, l0);
    split2(m2, m3, h1, l1);
    ((uint2*)g_ah)[(size_t)d * 64 + lane] = make_uint2(h0, h1);
    ((uint2*)g_al)[(size_t)d * 64 + lane] = make_uint2(l0, l1);

    // x_tgt half (cols 128..255)
    float4 xv = __ldg(x4 + (size_t)d * 32 + lane);
    split2(xv.x, xv.y, h0, l0);
    split2(xv.z, xv.w, h1, l1);
    ((uint2*)g_ah)[(size_t)d * 64 + 32 + lane] = make_uint2(h0, h1);
    ((uint2*)g_al)[(size_t)d * 64 + 32 + lane] = make_uint2(l0, l1);
}

// ---------------------------------------------------------------------------
// K3: prep_w — split weights to bf16 hi/lo, [n][kp] layout.
// ---------------------------------------------------------------------------
__global__ void prep_w(const float* __restrict__ w_l,
                       const float* __restrict__ w_r,
                       const float* __restrict__ w_out) {
    int t = blockIdx.x * 256 + threadIdx.x;       // 0..49151
    if (t < 32768) {
        int kp = t >> 8, n = t & 255;
        int k0 = 2 * kp;
        float v0, v1;
        if (k0 < 128) { v0 = w_l[k0 * 256 + n];         v1 = w_l[(k0 + 1) * 256 + n]; }
        else          { v0 = w_r[(k0 - 128) * 256 + n]; v1 = w_r[(k0 - 127) * 256 + n]; }
        uint32_t hi, lo; split2(v0, v1, hi, lo);
        g_wh[n * 128 + kp] = hi; g_wl[n * 128 + kp] = lo;
    } else {
        int u = t - 32768;
        int kp = u >> 7, n = u & 127;
        int k0 = 2 * kp;
        float v0 = w_out[k0 * 128 + n], v1 = w_out[(k0 + 1) * 128 + n];
        uint32_t hi, lo; split2(v0, v1, hi, lo);
        g_wohi[n * 128 + kp] = hi; g_wolo[n * 128 + kp] = lo;
    }
}

// ---------------------------------------------------------------------------
// K4: gemm1 — h = gelu(LN1( A @ W_cat + b_l )) -> g_hh/g_hl
// CTA 64 rows x 256 cols, 512 thr (16 warps: 2m x 8n, warp tile 32x32).
// K=256 in 4 chunks of 64, cp.async double buffered + ldmatrix (swizzled).
// ---------------------------------------------------------------------------
#define G1_SMEM 163840
__global__ __launch_bounds__(512, 1)
void gemm1_tc(const float* __restrict__ b_l,
              const float* __restrict__ ln_g,
              const float* __restrict__ ln_b) {
    extern __shared__ uint32_t sm[];
    __shared__ float sSum[64][8], sSq[64][8];
    uint32_t sb = smem_u32(sm);

    int tid = threadIdx.x, wid = tid >> 5, lane = tid & 31;
    int wm = wid >> 3, wn = wid & 7;
    int g = lane >> 2, t4 = lane & 3;
    int row0 = blockIdx.x * 64;

    int ar = tid >> 3, ac = tid & 7;
    int agrow = row0 + ar;
    uint32_t asz = (agrow < NUM_DST) ? 16u : 0u;
    uint32_t adst = (uint32_t)(ar * 8 + (ac ^ (ar & 7))) * 16;
    const uint32_t* asrcH = g_ah + (size_t)agrow * 128 + ac * 4;
    const uint32_t* asrcL = g_al + (size_t)agrow * 128 + ac * 4;

    float acc[2][4][4];
#pragma unroll
    for (int mt = 0; mt < 2; ++mt)
#pragma unroll
        for (int nt = 0; nt < 4; ++nt)
#pragma unroll
            for (int j = 0; j < 4; ++j) acc[mt][nt][j] = 0.f;

#define G1_ISSUE(kc, s) do {                                                      \
        uint32_t base = sb + (s) * 81920;                                         \
        CPA(base + adst, asrcH + (kc) * 32, asz);                                 \
        CPA(base + 8192 + adst, asrcL + (kc) * 32, asz);                          \
        for (int i = tid; i < 2048; i += 512) {                                   \
            int n_ = i >> 3, c_ = i & 7;                                          \
            uint32_t d_ = base + 16384 + (uint32_t)(n_ * 8 + (c_ ^ (n_ & 7))) * 16;\
            CPA16(d_, g_wh + n_ * 128 + (kc) * 32 + c_ * 4);                      \
            CPA16(d_ + 32768, g_wl + n_ * 128 + (kc) * 32 + c_ * 4);              \
        }                                                                         \
        CPCOMMIT();                                                               \
    } while (0)

    G1_ISSUE(0, 0);

    int arow = (lane & 15);
    int asel = lane >> 4;
    int wrow = ((lane >> 4) << 3) + (lane & 7);
    int wsel = (lane >> 3) & 1;

    for (int kc = 0; kc < 4; ++kc) {
        if (kc < 3) {
            G1_ISSUE(kc + 1, (kc + 1) & 1);
            asm volatile("cp.async.wait_group 1;" ::: "memory");
        } else {
            asm volatile("cp.async.wait_group 0;" ::: "memory");
        }
        __syncthreads();
        uint32_t base = sb + (kc & 1) * 81920;

#pragma unroll
        for (int ks = 0; ks < 4; ++ks) {
            uint32_t a_h[2][4], a_l[2][4], b_h[2][4], b_l2[2][4];
#pragma unroll
            for (int mt = 0; mt < 2; ++mt) {
                int r = wm * 32 + mt * 16 + arow;
                uint32_t ad = base + (uint32_t)(r * 8 + ((2 * ks + asel) ^ (r & 7))) * 16;
                LDSM4(a_h[mt], ad);
                LDSM4(a_l[mt], ad + 8192);
            }
#pragma unroll
            for (int ntp = 0; ntp < 2; ++ntp) {
                int n_ = wn * 32 + ntp * 16 + wrow;
                uint32_t wd = base + 16384 + (uint32_t)(n_ * 8 + ((2 * ks + wsel) ^ (n_ & 7))) * 16;
                LDSM4(b_h[ntp], wd);
                LDSM4(b_l2[ntp], wd + 32768);
            }
#pragma unroll
            for (int nt = 0; nt < 4; ++nt) {
                uint32_t bh0 = b_h[nt >> 1][(nt & 1) * 2], bh1 = b_h[nt >> 1][(nt & 1) * 2 + 1];
                uint32_t bl0 = b_l2[nt >> 1][(nt & 1) * 2], bl1 = b_l2[nt >> 1][(nt & 1) * 2 + 1];
#pragma unroll
                for (int mt = 0; mt < 2; ++mt) {
                    MMA(acc[mt][nt], a_h[mt][0], a_h[mt][1], a_h[mt][2], a_h[mt][3], bh0, bh1);
                    MMA(acc[mt][nt], a_h[mt][0], a_h[mt][1], a_h[mt][2], a_h[mt][3], bl0, bl1);
                    MMA(acc[mt][nt], a_l[mt][0], a_l[mt][1], a_l[mt][2], a_l[mt][3], bh0, bh1);
                }
            }
        }
        __syncthreads();
    }

    // ---- epilogue: bias, LN1, GELU, write split-bf16 h [row][kp] ----
#pragma unroll
    for (int nt = 0; nt < 4; ++nt) {
        int col = wn * 32 + nt * 8 + t4 * 2;
        float b0 = __ldg(b_l + col), b1 = __ldg(b_l + col + 1);
#pragma unroll
        for (int mt = 0; mt < 2; ++mt) {
            acc[mt][nt][0] += b0; acc[mt][nt][1] += b1;
            acc[mt][nt][2] += b0; acc[mt][nt][3] += b1;
        }
    }
#pragma unroll
    for (int mt = 0; mt < 2; ++mt)
#pragma unroll
        for (int ro = 0; ro < 2; ++ro) {
            float s = 0.f, q = 0.f;
#pragma unroll
            for (int nt = 0; nt < 4; ++nt) {
                float c0 = acc[mt][nt][ro * 2], c1 = acc[mt][nt][ro * 2 + 1];
                s += c0 + c1; q += c0 * c0 + c1 * c1;
            }
            s += __shfl_xor_sync(0xffffffffu, s, 1); q += __shfl_xor_sync(0xffffffffu, q, 1);
            s += __shfl_xor_sync(0xffffffffu, s, 2); q += __shfl_xor_sync(0xffffffffu, q, 2);
            if (t4 == 0) {
                int r = wm * 32 + mt * 16 + ro * 8 + g;
                sSum[r][wn] = s; sSq[r][wn] = q;
            }
        }
    __syncthreads();

#pragma unroll
    for (int mt = 0; mt < 2; ++mt)
#pragma unroll
        for (int ro = 0; ro < 2; ++ro) {
            int r = wm * 32 + mt * 16 + ro * 8 + g;
            int grow = row0 + r;
            float S = 0.f, SQ = 0.f;
#pragma unroll
            for (int j = 0; j < 8; ++j) { S += sSum[r][j]; SQ += sSq[r][j]; }
            float mu   = S * (1.0f / HID);
            float var  = SQ * (1.0f / HID) - mu * mu;
            float rstd = rsqrtf(var + 1e-5f);
            if (grow >= NUM_DST) continue;
#pragma unroll
            for (int nt = 0; nt < 4; ++nt) {
                int col = wn * 32 + nt * 8 + t4 * 2;
                float c0 = acc[mt][nt][ro * 2], c1 = acc[mt][nt][ro * 2 + 1];
                float v0 = gelu_exact((c0 - mu) * rstd * __ldg(ln_g + col)     + __ldg(ln_b + col));
                float v1 = gelu_exact((c1 - mu) * rstd * __ldg(ln_g + col + 1) + __ldg(ln_b + col + 1));
                uint32_t hi, lo; split2(v0, v1, hi, lo);
                g_hh[(size_t)grow * 128 + (col >> 1)] = hi;
                g_hl[(size_t)grow * 128 + (col >> 1)] = lo;
            }
        }
}

// ---------------------------------------------------------------------------
// K5: gemm2 — out = LN2( h @ W_out + b_out ) -> d_out fp32
// ---------------------------------------------------------------------------
#define G2_SMEM 98304
__global__ __launch_bounds__(512, 2)
void gemm2_tc(const float* __restrict__ b_out,
              const float* __restrict__ ln_g,
              const float* __restrict__ ln_b,
              float* __restrict__ out) {
    extern __shared__ uint32_t sm[];
    __shared__ float sSum[64][8], sSq[64][8];
    uint32_t sb = smem_u32(sm);

    int tid = threadIdx.x, wid = tid >> 5, lane = tid & 31;
    int wm = wid >> 3, wn = wid & 7;
    int g = lane >> 2, t4 = lane & 3;
    int row0 = blockIdx.x * 64;

    int ar = tid >> 3, ac = tid & 7;
    int agrow = row0 + ar;
    uint32_t asz = (agrow < NUM_DST) ? 16u : 0u;
    uint32_t adst = (uint32_t)(ar * 8 + (ac ^ (ar & 7))) * 16;
    const uint32_t* asrcH = g_hh + (size_t)agrow * 128 + ac * 4;
    const uint32_t* asrcL = g_hl + (size_t)agrow * 128 + ac * 4;

    float acc[2][2][4];
#pragma unroll
    for (int mt = 0; mt < 2; ++mt)
#pragma unroll
        for (int nt = 0; nt < 2; ++nt)
#pragma unroll
            for (int j = 0; j < 4; ++j) acc[mt][nt][j] = 0.f;

#define G2_ISSUE(kc, s) do {                                                      \
        uint32_t base = sb + (s) * 49152;                                         \
        CPA(base + adst, asrcH + (kc) * 32, asz);                                 \
        CPA(base + 8192 + adst, asrcL + (kc) * 32, asz);                          \
        for (int i = tid; i < 1024; i += 512) {                                   \
            int n_ = i >> 3, c_ = i & 7;                                          \
            uint32_t d_ = base + 16384 + (uint32_t)(n_ * 8 + (c_ ^ (n_ & 7))) * 16;\
            CPA16(d_, g_wohi + n_ * 128 + (kc) * 32 + c_ * 4);                    \
            CPA16(d_ + 16384, g_wolo + n_ * 128 + (kc) * 32 + c_ * 4);            \
        }                                                                         \
        CPCOMMIT();                                                               \
    } while (0)

    G2_ISSUE(0, 0);

    int arow = (lane & 15);
    int asel = lane >> 4;
    int wrow = ((lane >> 4) << 3) + (lane & 7);
    int wsel = (lane >> 3) & 1;

    for (int kc = 0; kc < 4; ++kc) {
        if (kc < 3) {
            G2_ISSUE(kc + 1, (kc + 1) & 1);
            asm volatile("cp.async.wait_group 1;" ::: "memory");
        } else {
            asm volatile("cp.async.wait_group 0;" ::: "memory");
        }
        __syncthreads();
        uint32_t base = sb + (kc & 1) * 49152;

#pragma unroll
        for (int ks = 0; ks < 4; ++ks) {
            uint32_t a_h[2][4], a_l[2][4], b_h[4], b_l2[4];
#pragma unroll
            for (int mt = 0; mt < 2; ++mt) {
                int r = wm * 32 + mt * 16 + arow;
                uint32_t ad = base + (uint32_t)(r * 8 + ((2 * ks + asel) ^ (r & 7))) * 16;
                LDSM4(a_h[mt], ad);
                LDSM4(a_l[mt], ad + 8192);
            }
            {
                int n_ = wn * 16 + wrow;
                uint32_t wd = base + 16384 + (uint32_t)(n_ * 8 + ((2 * ks + wsel) ^ (n_ & 7))) * 16;
                LDSM4(b_h, wd);
                LDSM4(b_l2, wd + 16384);
            }
#pragma unroll
            for (int nt = 0; nt < 2; ++nt) {
                uint32_t bh0 = b_h[nt * 2], bh1 = b_h[nt * 2 + 1];
                uint32_t bl0 = b_l2[nt * 2], bl1 = b_l2[nt * 2 + 1];
#pragma unroll
                for (int mt = 0; mt < 2; ++mt) {
                    MMA(acc[mt][nt], a_h[mt][0], a_h[mt][1], a_h[mt][2], a_h[mt][3], bh0, bh1);
                    MMA(acc[mt][nt], a_h[mt][0], a_h[mt][1], a_h[mt][2], a_h[mt][3], bl0, bl1);
                    MMA(acc[mt][nt], a_l[mt][0], a_l[mt][1], a_l[mt][2], a_l[mt][3], bh0, bh1);
                }
            }
        }
        __syncthreads();
    }

    // ---- epilogue: bias, LN2, fp32 out ----
#pragma unroll
    for (int nt = 0; nt < 2; ++nt) {
        int col = wn * 16 + nt * 8 + t4 * 2;
        float b0 = __ldg(b_out + col), b1 = __ldg(b_out + col + 1);
#pragma unroll
        for (int mt = 0; mt < 2; ++mt) {
            acc[mt][nt][0] += b0; acc[mt][nt][1] += b1;
            acc[mt][nt][2] += b0; acc[mt][nt][3] += b1;
        }
    }
#pragma unroll
    for (int mt = 0; mt < 2; ++mt)
#pragma unroll
        for (int ro = 0; ro < 2; ++ro) {
            float s = 0.f, q = 0.f;
#pragma unroll
            for (int nt = 0; nt < 2; ++nt) {
                float c0 = acc[mt][nt][ro * 2], c1 = acc[mt][nt][ro * 2 + 1];
                s += c0 + c1; q += c0 * c0 + c1 * c1;
            }
            s += __shfl_xor_sync(0xffffffffu, s, 1); q += __shfl_xor_sync(0xffffffffu, q, 1);
            s += __shfl_xor_sync(0xffffffffu, s, 2); q += __shfl_xor_sync(0xffffffffu, q, 2);
            if (t4 == 0) {
                int r = wm * 32 + mt * 16 + ro * 8 + g;
                sSum[r][wn] = s; sSq[r][wn] = q;
            }
        }
    __syncthreads();

#pragma unroll
    for (int mt = 0; mt < 2; ++mt)
#pragma unroll
        for (int ro = 0; ro < 2; ++ro) {
            int r = wm * 32 + mt * 16 + ro * 8 + g;
            int grow = row0 + r;
            float S = 0.f, SQ = 0.f;
#pragma unroll
            for (int j = 0; j < 8; ++j) { S += sSum[r][j]; SQ += sSq[r][j]; }
            float mu   = S * (1.0f / OUT_DIM);
            float var  = SQ * (1.0f / OUT_DIM) - mu * mu;
            float rstd = rsqrtf(var + 1e-5f);
            if (grow >= NUM_DST) continue;
#pragma unroll
            for (int nt = 0; nt < 2; ++nt) {
                int col = wn * 16 + nt * 8 + t4 * 2;
                float c0 = acc[mt][nt][ro * 2], c1 = acc[mt][nt][ro * 2 + 1];
                float2 o;
                o.x = (c0 - mu) * rstd * __ldg(ln_g + col)     + __ldg(ln_b + col);
                o.y = (c1 - mu) * rstd * __ldg(ln_g + col + 1) + __ldg(ln_b + col + 1);
                *(float2*)(out + (size_t)grow * 128 + col) = o;
            }
        }
}

// ---------------------------------------------------------------------------
extern "C" void kernel_launch(void* const* d_in, const int* in_sizes, int n_in,
                              void* d_out, int out_size) {
    const float* x     = (const float*)d_in[0];
    const float* w_l   = (const float*)d_in[1];
    const float* b_l   = (const float*)d_in[2];
    const float* w_r   = (const float*)d_in[3];
    const float* ln1_g = (const float*)d_in[4];
    const float* ln1_b = (const float*)d_in[5];
    const float* w_out = (const float*)d_in[6];
    const float* b_out = (const float*)d_in[7];
    const float* ln2_g = (const float*)d_in[8];
    const float* ln2_b = (const float*)d_in[9];
    const int*   esrc  = (const int*)d_in[10];
    const int*   edst  = (const int*)d_in[11];
    float* out = (float*)d_out;

    cudaFuncSetAttribute(gemm1_tc, cudaFuncAttributeMaxDynamicSharedMemorySize, G1_SMEM);
    cudaFuncSetAttribute(gemm2_tc, cudaFuncAttributeMaxDynamicSharedMemorySize, G2_SMEM);

    zero_deg<<<(NUM_DST + 255) / 256, 256>>>();
    fill_kernel<<<(NUM_EDGES + 255) / 256, 256>>>(esrc, edst);
    prep_w<<<192, 256>>>(w_l, w_r, w_out);
    agg_kernel<<<(NUM_DST + 7) / 8, 256>>>(x);

    gemm1_tc<<<NRB, 512, G1_SMEM>>>(b_l, ln1_g, ln1_b);
    gemm2_tc<<<NRB, 512, G2_SMEM>>>(b_out, ln2_g, ln2_b, out);
}

// round 10
// speedup vs baseline: 1.4139x; 1.4139x over previous
#include <cuda_runtime.h>
#include <cuda_bf16.h>
#include <math.h>
#include <stdint.h>

#define NUM_SRC   200000
#define NUM_DST   100000
#define NUM_EDGES 1600000
#define IN_DIM    128
#define HID       256
#define OUT_DIM   128
#define NRB       1563      // ceil(NUM_DST/64)
#define BUCKET_CAP 64

// ---------------------------------------------------------------------------
// Scratch (__device__ globals; no allocation allowed)
// ---------------------------------------------------------------------------
__device__ __align__(16) int      g_deg[NUM_DST];                      // 0.4 MB
__device__ __align__(16) int      g_bucket[(size_t)NUM_DST * BUCKET_CAP]; // 25.6 MB
__device__ __align__(16) uint32_t g_ah[(size_t)NUM_DST * 128];         // A=[mean|x] bf16 hi, [row][kp]
__device__ __align__(16) uint32_t g_al[(size_t)NUM_DST * 128];         // A lo
__device__ __align__(16) uint32_t g_hh[(size_t)NUM_DST * 128];         // h bf16 hi, [row][kp]
__device__ __align__(16) uint32_t g_hl[(size_t)NUM_DST * 128];         // h lo
__device__ __align__(16) uint32_t g_wh[256 * 128];                     // W_cat hi  [n][kp]
__device__ __align__(16) uint32_t g_wl[256 * 128];                     // W_cat lo
__device__ __align__(16) uint32_t g_wohi[128 * 128];                   // W_out hi  [n][kp]
__device__ __align__(16) uint32_t g_wolo[128 * 128];                   // W_out lo

// ---------------------------------------------------------------------------
// helpers
// ---------------------------------------------------------------------------
__device__ __forceinline__ uint32_t smem_u32(const void* p) {
    uint32_t a;
    asm("{ .reg .u64 t; cvta.to.shared.u64 t, %1; cvt.u32.u64 %0, t; }" : "=r"(a) : "l"(p));
    return a;
}
__device__ __forceinline__ void split2(float a0, float a1, uint32_t& hi, uint32_t& lo) {
    __nv_bfloat16 h0 = __float2bfloat16(a0), h1 = __float2bfloat16(a1);
    __nv_bfloat16 l0 = __float2bfloat16(a0 - __bfloat162float(h0));
    __nv_bfloat16 l1 = __float2bfloat16(a1 - __bfloat162float(h1));
    __nv_bfloat162 H; H.x = h0; H.y = h1;
    __nv_bfloat162 L; L.x = l0; L.y = l1;
    hi = *(uint32_t*)&H; lo = *(uint32_t*)&L;
}
__device__ __forceinline__ float gelu_exact(float t) {
    return 0.5f * t * (1.0f + erff(t * 0.70710678118654752f));
}

#define MMA(c, A0, A1, A2, A3, B0, B1)                                          \
    asm("mma.sync.aligned.m16n8k16.row.col.f32.bf16.bf16.f32 "                  \
        "{%0,%1,%2,%3},{%4,%5,%6,%7},{%8,%9},{%0,%1,%2,%3};"                    \
        : "+f"((c)[0]), "+f"((c)[1]), "+f"((c)[2]), "+f"((c)[3])                \
        : "r"(A0), "r"(A1), "r"(A2), "r"(A3), "r"(B0), "r"(B1))

#define LDSM4(R, addr)                                                          \
    asm volatile("ldmatrix.sync.aligned.m8n8.x4.shared.b16 {%0,%1,%2,%3}, [%4];"\
        : "=r"((R)[0]), "=r"((R)[1]), "=r"((R)[2]), "=r"((R)[3]) : "r"(addr))

#define CPA(dst, src, sz)                                                       \
    asm volatile("cp.async.ca.shared.global [%0], [%1], 16, %2;"                \
        :: "r"(dst), "l"(src), "r"(sz))
#define CPA16(dst, src)                                                         \
    asm volatile("cp.async.ca.shared.global [%0], [%1], 16;" :: "r"(dst), "l"(src))
#define CPCOMMIT() asm volatile("cp.async.commit_group;" ::: "memory")

// ---------------------------------------------------------------------------
// K0: zero degree counters
// ---------------------------------------------------------------------------
__global__ void zero_deg() {
    int i = blockIdx.x * 256 + threadIdx.x;
    if (i < NUM_DST) g_deg[i] = 0;
}

// ---------------------------------------------------------------------------
// K1: fill buckets — per edge: slot = atomicAdd(deg[dst]), bucket[dst][slot]=src
// ---------------------------------------------------------------------------
__global__ void fill_kernel(const int* __restrict__ esrc,
                            const int* __restrict__ edst) {
    int e = blockIdx.x * 256 + threadIdx.x;
    if (e >= NUM_EDGES) return;
    int s = __ldg(esrc + e);
    int d = __ldg(edst + e);
    int pos = atomicAdd(&g_deg[d], 1);
    if (pos < BUCKET_CAP)
        g_bucket[(size_t)d * BUCKET_CAP + pos] = s;
}

// ---------------------------------------------------------------------------
// K2: aggregate, column-split. Pass `half` covers x cols [half*64, half*64+64).
// Warp per dst, float2 (8B) per lane. The live half of x is 51.2 MB ->
// L2-resident, so the random gather is served from L2, not DRAM.
// ---------------------------------------------------------------------------
__global__ void agg_half(const float* __restrict__ x, int half) {
    int d    = blockIdx.x * 8 + (threadIdx.x >> 5);
    int lane = threadIdx.x & 31;
    if (d >= NUM_DST) return;

    int degT = g_deg[d];
    int deg  = min(degT, BUCKET_CAP);
    const int* lst = g_bucket + (size_t)d * BUCKET_CAP;
    const float2* x2 = (const float2*)x;       // row = 64 float2
    int off = half * 32 + lane;

    float s0 = 0.f, s1 = 0.f;
    int i = 0;
    for (; i + 8 <= deg; i += 8) {
        int e0 = __ldg(lst + i),     e1 = __ldg(lst + i + 1);
        int e2 = __ldg(lst + i + 2), e3 = __ldg(lst + i + 3);
        int e4 = __ldg(lst + i + 4), e5 = __ldg(lst + i + 5);
        int e6 = __ldg(lst + i + 6), e7 = __ldg(lst + i + 7);
        float2 v0 = __ldg(x2 + (size_t)e0 * 64 + off);
        float2 v1 = __ldg(x2 + (size_t)e1 * 64 + off);
        float2 v2 = __ldg(x2 + (size_t)e2 * 64 + off);
        float2 v3 = __ldg(x2 + (size_t)e3 * 64 + off);
        float2 v4 = __ldg(x2 + (size_t)e4 * 64 + off);
        float2 v5 = __ldg(x2 + (size_t)e5 * 64 + off);
        float2 v6 = __ldg(x2 + (size_t)e6 * 64 + off);
        float2 v7 = __ldg(x2 + (size_t)e7 * 64 + off);
        s0 += v0.x + v1.x + v2.x + v3.x + v4.x + v5.x + v6.x + v7.x;
        s1 += v0.y + v1.y + v2.y + v3.y + v4.y + v5.y + v6.y + v7.y;
    }
    for (; i + 4 <= deg; i += 4) {
        int e0 = __ldg(lst + i),     e1 = __ldg(lst + i + 1);
        int e2 = __ldg(lst + i + 2), e3 = __ldg(lst + i + 3);
        float2 v0 = __ldg(x2 + (size_t)e0 * 64 + off);
        float2 v1 = __ldg(x2 + (size_t)e1 * 64 + off);
        float2 v2 = __ldg(x2 + (size_t)e2 * 64 + off);
        float2 v3 = __ldg(x2 + (size_t)e3 * 64 + off);
        s0 += v0.x + v1.x + v2.x + v3.x;
        s1 += v0.y + v1.y + v2.y + v3.y;
    }
    for (; i < deg; ++i) {
        int e = __ldg(lst + i);
        float2 v = __ldg(x2 + (size_t)e * 64 + off);
        s0 += v.x; s1 += v.y;
    }

    float inv = 1.0f / fmaxf((float)degT, 1.0f);
    uint32_t hi, lo;
    split2(s0 * inv, s1 * inv, hi, lo);
    g_ah[(size_t)d * 128 + half * 32 + lane] = hi;
    g_al[(size_t)d * 128 + half * 32 + lane] = lo;

    // x_tgt half: x col c -> A col 128+c -> kp = 64 + half*32 + lane
    float2 xv = __ldg(x2 + (size_t)d * 64 + off);
    split2(xv.x, xv.y, hi, lo);
    g_ah[(size_t)d * 128 + 64 + half * 32 + lane] = hi;
    g_al[(size_t)d * 128 + 64 + half * 32 + lane] = lo;
}

// ---------------------------------------------------------------------------
// K3: prep_w — split weights to bf16 hi/lo, [n][kp] layout.
// ---------------------------------------------------------------------------
__global__ void prep_w(const float* __restrict__ w_l,
                       const float* __restrict__ w_r,
                       const float* __restrict__ w_out) {
    int t = blockIdx.x * 256 + threadIdx.x;       // 0..49151
    if (t < 32768) {
        int kp = t >> 8, n = t & 255;
        int k0 = 2 * kp;
        float v0, v1;
        if (k0 < 128) { v0 = w_l[k0 * 256 + n];         v1 = w_l[(k0 + 1) * 256 + n]; }
        else          { v0 = w_r[(k0 - 128) * 256 + n]; v1 = w_r[(k0 - 127) * 256 + n]; }
        uint32_t hi, lo; split2(v0, v1, hi, lo);
        g_wh[n * 128 + kp] = hi; g_wl[n * 128 + kp] = lo;
    } else {
        int u = t - 32768;
        int kp = u >> 7, n = u & 127;
        int k0 = 2 * kp;
        float v0 = w_out[k0 * 128 + n], v1 = w_out[(k0 + 1) * 128 + n];
        uint32_t hi, lo; split2(v0, v1, hi, lo);
        g_wohi[n * 128 + kp] = hi; g_wolo[n * 128 + kp] = lo;
    }
}

// ---------------------------------------------------------------------------
// K4: gemm1 — h = gelu(LN1( A @ W_cat + b_l )) -> g_hh/g_hl
// CTA 64 rows x 256 cols, 512 thr (16 warps: 2m x 8n, warp tile 32x32).
// K=256 in 4 chunks of 64, cp.async double buffered + ldmatrix (swizzled).
// ---------------------------------------------------------------------------
#define G1_SMEM 163840
__global__ __launch_bounds__(512, 1)
void gemm1_tc(const float* __restrict__ b_l,
              const float* __restrict__ ln_g,
              const float* __restrict__ ln_b) {
    extern __shared__ uint32_t sm[];
    __shared__ float sSum[64][8], sSq[64][8];
    uint32_t sb = smem_u32(sm);

    int tid = threadIdx.x, wid = tid >> 5, lane = tid & 31;
    int wm = wid >> 3, wn = wid & 7;
    int g = lane >> 2, t4 = lane & 3;
    int row0 = blockIdx.x * 64;

    int ar = tid >> 3, ac = tid & 7;
    int agrow = row0 + ar;
    uint32_t asz = (agrow < NUM_DST) ? 16u : 0u;
    uint32_t adst = (uint32_t)(ar * 8 + (ac ^ (ar & 7))) * 16;
    const uint32_t* asrcH = g_ah + (size_t)agrow * 128 + ac * 4;
    const uint32_t* asrcL = g_al + (size_t)agrow * 128 + ac * 4;

    float acc[2][4][4];
#pragma unroll
    for (int mt = 0; mt < 2; ++mt)
#pragma unroll
        for (int nt = 0; nt < 4; ++nt)
#pragma unroll
            for (int j = 0; j < 4; ++j) acc[mt][nt][j] = 0.f;

#define G1_ISSUE(kc, s) do {                                                      \
        uint32_t base = sb + (s) * 81920;                                         \
        CPA(base + adst, asrcH + (kc) * 32, asz);                                 \
        CPA(base + 8192 + adst, asrcL + (kc) * 32, asz);                          \
        for (int i = tid; i < 2048; i += 512) {                                   \
            int n_ = i >> 3, c_ = i & 7;                                          \
            uint32_t d_ = base + 16384 + (uint32_t)(n_ * 8 + (c_ ^ (n_ & 7))) * 16;\
            CPA16(d_, g_wh + n_ * 128 + (kc) * 32 + c_ * 4);                      \
            CPA16(d_ + 32768, g_wl + n_ * 128 + (kc) * 32 + c_ * 4);              \
        }                                                                         \
        CPCOMMIT();                                                               \
    } while (0)

    G1_ISSUE(0, 0);

    int arow = (lane & 15);
    int asel = lane >> 4;
    int wrow = ((lane >> 4) << 3) + (lane & 7);
    int wsel = (lane >> 3) & 1;

    for (int kc = 0; kc < 4; ++kc) {
        if (kc < 3) {
            G1_ISSUE(kc + 1, (kc + 1) & 1);
            asm volatile("cp.async.wait_group 1;" ::: "memory");
        } else {
            asm volatile("cp.async.wait_group 0;" ::: "memory");
        }
        __syncthreads();
        uint32_t base = sb + (kc & 1) * 81920;

#pragma unroll
        for (int ks = 0; ks < 4; ++ks) {
            uint32_t a_h[2][4], a_l[2][4], b_h[2][4], b_l2[2][4];
#pragma unroll
            for (int mt = 0; mt < 2; ++mt) {
                int r = wm * 32 + mt * 16 + arow;
                uint32_t ad = base + (uint32_t)(r * 8 + ((2 * ks + asel) ^ (r & 7))) * 16;
                LDSM4(a_h[mt], ad);
                LDSM4(a_l[mt], ad + 8192);
            }
#pragma unroll
            for (int ntp = 0; ntp < 2; ++ntp) {
                int n_ = wn * 32 + ntp * 16 + wrow;
                uint32_t wd = base + 16384 + (uint32_t)(n_ * 8 + ((2 * ks + wsel) ^ (n_ & 7))) * 16;
                LDSM4(b_h[ntp], wd);
                LDSM4(b_l2[ntp], wd + 32768);
            }
#pragma unroll
            for (int nt = 0; nt < 4; ++nt) {
                uint32_t bh0 = b_h[nt >> 1][(nt & 1) * 2], bh1 = b_h[nt >> 1][(nt & 1) * 2 + 1];
                uint32_t bl0 = b_l2[nt >> 1][(nt & 1) * 2], bl1 = b_l2[nt >> 1][(nt & 1) * 2 + 1];
#pragma unroll
                for (int mt = 0; mt < 2; ++mt) {
                    MMA(acc[mt][nt], a_h[mt][0], a_h[mt][1], a_h[mt][2], a_h[mt][3], bh0, bh1);
                    MMA(acc[mt][nt], a_h[mt][0], a_h[mt][1], a_h[mt][2], a_h[mt][3], bl0, bl1);
                    MMA(acc[mt][nt], a_l[mt][0], a_l[mt][1], a_l[mt][2], a_l[mt][3], bh0, bh1);
                }
            }
        }
        __syncthreads();
    }

    // ---- epilogue: bias, LN1, GELU, write split-bf16 h [row][kp] ----
#pragma unroll
    for (int nt = 0; nt < 4; ++nt) {
        int col = wn * 32 + nt * 8 + t4 * 2;
        float b0 = __ldg(b_l + col), b1 = __ldg(b_l + col + 1);
#pragma unroll
        for (int mt = 0; mt < 2; ++mt) {
            acc[mt][nt][0] += b0; acc[mt][nt][1] += b1;
            acc[mt][nt][2] += b0; acc[mt][nt][3] += b1;
        }
    }
#pragma unroll
    for (int mt = 0; mt < 2; ++mt)
#pragma unroll
        for (int ro = 0; ro < 2; ++ro) {
            float s = 0.f, q = 0.f;
#pragma unroll
            for (int nt = 0; nt < 4; ++nt) {
                float c0 = acc[mt][nt][ro * 2], c1 = acc[mt][nt][ro * 2 + 1];
                s += c0 + c1; q += c0 * c0 + c1 * c1;
            }
            s += __shfl_xor_sync(0xffffffffu, s, 1); q += __shfl_xor_sync(0xffffffffu, q, 1);
            s += __shfl_xor_sync(0xffffffffu, s, 2); q += __shfl_xor_sync(0xffffffffu, q, 2);
            if (t4 == 0) {
                int r = wm * 32 + mt * 16 + ro * 8 + g;
                sSum[r][wn] = s; sSq[r][wn] = q;
            }
        }
    __syncthreads();

#pragma unroll
    for (int mt = 0; mt < 2; ++mt)
#pragma unroll
        for (int ro = 0; ro < 2; ++ro) {
            int r = wm * 32 + mt * 16 + ro * 8 + g;
            int grow = row0 + r;
            float S = 0.f, SQ = 0.f;
#pragma unroll
            for (int j = 0; j < 8; ++j) { S += sSum[r][j]; SQ += sSq[r][j]; }
            float mu   = S * (1.0f / HID);
            float var  = SQ * (1.0f / HID) - mu * mu;
            float rstd = rsqrtf(var + 1e-5f);
            if (grow >= NUM_DST) continue;
#pragma unroll
            for (int nt = 0; nt < 4; ++nt) {
                int col = wn * 32 + nt * 8 + t4 * 2;
                float c0 = acc[mt][nt][ro * 2], c1 = acc[mt][nt][ro * 2 + 1];
                float v0 = gelu_exact((c0 - mu) * rstd * __ldg(ln_g + col)     + __ldg(ln_b + col));
                float v1 = gelu_exact((c1 - mu) * rstd * __ldg(ln_g + col + 1) + __ldg(ln_b + col + 1));
                uint32_t hi, lo; split2(v0, v1, hi, lo);
                g_hh[(size_t)grow * 128 + (col >> 1)] = hi;
                g_hl[(size_t)grow * 128 + (col >> 1)] = lo;
            }
        }
}

// ---------------------------------------------------------------------------
// K5: gemm2 — out = LN2( h @ W_out + b_out ) -> d_out fp32
// ---------------------------------------------------------------------------
#define G2_SMEM 98304
__global__ __launch_bounds__(512, 2)
void gemm2_tc(const float* __restrict__ b_out,
              const float* __restrict__ ln_g,
              const float* __restrict__ ln_b,
              float* __restrict__ out) {
    extern __shared__ uint32_t sm[];
    __shared__ float sSum[64][8], sSq[64][8];
    uint32_t sb = smem_u32(sm);

    int tid = threadIdx.x, wid = tid >> 5, lane = tid & 31;
    int wm = wid >> 3, wn = wid & 7;
    int g = lane >> 2, t4 = lane & 3;
    int row0 = blockIdx.x * 64;

    int ar = tid >> 3, ac = tid & 7;
    int agrow = row0 + ar;
    uint32_t asz = (agrow < NUM_DST) ? 16u : 0u;
    uint32_t adst = (uint32_t)(ar * 8 + (ac ^ (ar & 7))) * 16;
    const uint32_t* asrcH = g_hh + (size_t)agrow * 128 + ac * 4;
    const uint32_t* asrcL = g_hl + (size_t)agrow * 128 + ac * 4;

    float acc[2][2][4];
#pragma unroll
    for (int mt = 0; mt < 2; ++mt)
#pragma unroll
        for (int nt = 0; nt < 2; ++nt)
#pragma unroll
            for (int j = 0; j < 4; ++j) acc[mt][nt][j] = 0.f;

#define G2_ISSUE(kc, s) do {                                                      \
        uint32_t base = sb + (s) * 49152;                                         \
        CPA(base + adst, asrcH + (kc) * 32, asz);                                 \
        CPA(base + 8192 + adst, asrcL + (kc) * 32, asz);                          \
        for (int i = tid; i < 1024; i += 512) {                                   \
            int n_ = i >> 3, c_ = i & 7;                                          \
            uint32_t d_ = base + 16384 + (uint32_t)(n_ * 8 + (c_ ^ (n_ & 7))) * 16;\
            CPA16(d_, g_wohi + n_ * 128 + (kc) * 32 + c_ * 4);                    \
            CPA16(d_ + 16384, g_wolo + n_ * 128 + (kc) * 32 + c_ * 4);            \
        }                                                                         \
        CPCOMMIT();                                                               \
    } while (0)

    G2_ISSUE(0, 0);

    int arow = (lane & 15);
    int asel = lane >> 4;
    int wrow = ((lane >> 4) << 3) + (lane & 7);
    int wsel = (lane >> 3) & 1;

    for (int kc = 0; kc < 4; ++kc) {
        if (kc < 3) {
            G2_ISSUE(kc + 1, (kc + 1) & 1);
            asm volatile("cp.async.wait_group 1;" ::: "memory");
        } else {
            asm volatile("cp.async.wait_group 0;" ::: "memory");
        }
        __syncthreads();
        uint32_t base = sb + (kc & 1) * 49152;

#pragma unroll
        for (int ks = 0; ks < 4; ++ks) {
            uint32_t a_h[2][4], a_l[2][4], b_h[4], b_l2[4];
#pragma unroll
            for (int mt = 0; mt < 2; ++mt) {
                int r = wm * 32 + mt * 16 + arow;
                uint32_t ad = base + (uint32_t)(r * 8 + ((2 * ks + asel) ^ (r & 7))) * 16;
                LDSM4(a_h[mt], ad);
                LDSM4(a_l[mt], ad + 8192);
            }
            {
                int n_ = wn * 16 + wrow;
                uint32_t wd = base + 16384 + (uint32_t)(n_ * 8 + ((2 * ks + wsel) ^ (n_ & 7))) * 16;
                LDSM4(b_h, wd);
                LDSM4(b_l2, wd + 16384);
            }
#pragma unroll
            for (int nt = 0; nt < 2; ++nt) {
                uint32_t bh0 = b_h[nt * 2], bh1 = b_h[nt * 2 + 1];
                uint32_t bl0 = b_l2[nt * 2], bl1 = b_l2[nt * 2 + 1];
#pragma unroll
                for (int mt = 0; mt < 2; ++mt) {
                    MMA(acc[mt][nt], a_h[mt][0], a_h[mt][1], a_h[mt][2], a_h[mt][3], bh0, bh1);
                    MMA(acc[mt][nt], a_h[mt][0], a_h[mt][1], a_h[mt][2], a_h[mt][3], bl0, bl1);
                    MMA(acc[mt][nt], a_l[mt][0], a_l[mt][1], a_l[mt][2], a_l[mt][3], bh0, bh1);
                }
            }
        }
        __syncthreads();
    }

    // ---- epilogue: bias, LN2, fp32 out ----
#pragma unroll
    for (int nt = 0; nt < 2; ++nt) {
        int col = wn * 16 + nt * 8 + t4 * 2;
        float b0 = __ldg(b_out + col), b1 = __ldg(b_out + col + 1);
#pragma unroll
        for (int mt = 0; mt < 2; ++mt) {
            acc[mt][nt][0] += b0; acc[mt][nt][1] += b1;
            acc[mt][nt][2] += b0; acc[mt][nt][3] += b1;
        }
    }
#pragma unroll
    for (int mt = 0; mt < 2; ++mt)
#pragma unroll
        for (int ro = 0; ro < 2; ++ro) {
            float s = 0.f, q = 0.f;
#pragma unroll
            for (int nt = 0; nt < 2; ++nt) {
                float c0 = acc[mt][nt][ro * 2], c1 = acc[mt][nt][ro * 2 + 1];
                s += c0 + c1; q += c0 * c0 + c1 * c1;
            }
            s += __shfl_xor_sync(0xffffffffu, s, 1); q += __shfl_xor_sync(0xffffffffu, q, 1);
            s += __shfl_xor_sync(0xffffffffu, s, 2); q += __shfl_xor_sync(0xffffffffu, q, 2);
            if (t4 == 0) {
                int r = wm * 32 + mt * 16 + ro * 8 + g;
                sSum[r][wn] = s; sSq[r][wn] = q;
            }
        }
    __syncthreads();

#pragma unroll
    for (int mt = 0; mt < 2; ++mt)
#pragma unroll
        for (int ro = 0; ro < 2; ++ro) {
            int r = wm * 32 + mt * 16 + ro * 8 + g;
            int grow = row0 + r;
            float S = 0.f, SQ = 0.f;
#pragma unroll
            for (int j = 0; j < 8; ++j) { S += sSum[r][j]; SQ += sSq[r][j]; }
            float mu   = S * (1.0f / OUT_DIM);
            float var  = SQ * (1.0f / OUT_DIM) - mu * mu;
            float rstd = rsqrtf(var + 1e-5f);
            if (grow >= NUM_DST) continue;
#pragma unroll
            for (int nt = 0; nt < 2; ++nt) {
                int col = wn * 16 + nt * 8 + t4 * 2;
                float c0 = acc[mt][nt][ro * 2], c1 = acc[mt][nt][ro * 2 + 1];
                float2 o;
                o.x = (c0 - mu) * rstd * __ldg(ln_g + col)     + __ldg(ln_b + col);
                o.y = (c1 - mu) * rstd * __ldg(ln_g + col + 1) + __ldg(ln_b + col + 1);
                *(float2*)(out + (size_t)grow * 128 + col) = o;
            }
        }
}

// ---------------------------------------------------------------------------
extern "C" void kernel_launch(void* const* d_in, const int* in_sizes, int n_in,
                              void* d_out, int out_size) {
    const float* x     = (const float*)d_in[0];
    const float* w_l   = (const float*)d_in[1];
    const float* b_l   = (const float*)d_in[2];
    const float* w_r   = (const float*)d_in[3];
    const float* ln1_g = (const float*)d_in[4];
    const float* ln1_b = (const float*)d_in[5];
    const float* w_out = (const float*)d_in[6];
    const float* b_out = (const float*)d_in[7];
    const float* ln2_g = (const float*)d_in[8];
    const float* ln2_b = (const float*)d_in[9];
    const int*   esrc  = (const int*)d_in[10];
    const int*   edst  = (const int*)d_in[11];
    float* out = (float*)d_out;

    cudaFuncSetAttribute(gemm1_tc, cudaFuncAttributeMaxDynamicSharedMemorySize, G1_SMEM);
    cudaFuncSetAttribute(gemm2_tc, cudaFuncAttributeMaxDynamicSharedMemorySize, G2_SMEM);

    zero_deg<<<(NUM_DST + 255) / 256, 256>>>();
    fill_kernel<<<(NUM_EDGES + 255) / 256, 256>>>(esrc, edst);
    prep_w<<<192, 256>>>(w_l, w_r, w_out);
    agg_half<<<(NUM_DST + 7) / 8, 256>>>(x, 0);
    agg_half<<<(NUM_DST + 7) / 8, 256>>>(x, 1);

    gemm1_tc<<<NRB, 512, G1_SMEM>>>(b_l, ln1_g, ln1_b);
    gemm2_tc<<<NRB, 512, G2_SMEM>>>(b_out, ln2_g, ln2_b, out);
}

// round 11
// speedup vs baseline: 1.5069x; 1.0658x over previous
#include <cuda_runtime.h>
#include <cuda_bf16.h>
#include <math.h>
#include <stdint.h>

#define NUM_SRC   200000
#define NUM_DST   100000
#define NUM_EDGES 1600000
#define IN_DIM    128
#define HID       256
#define OUT_DIM   128
#define NRB       1563      // ceil(NUM_DST/64)
#define BUCKET_CAP 64

// ---------------------------------------------------------------------------
// Scratch (__device__ globals; no allocation allowed)
// ---------------------------------------------------------------------------
__device__ __align__(16) int      g_deg[NUM_DST];                      // 0.4 MB
__device__ __align__(16) int      g_bucket[(size_t)NUM_DST * BUCKET_CAP]; // 25.6 MB
__device__ __align__(16) uint32_t g_ah[(size_t)NUM_DST * 128];         // A=[mean|x] bf16 hi, [row][kp]
__device__ __align__(16) uint32_t g_al[(size_t)NUM_DST * 128];         // A lo
__device__ __align__(16) uint32_t g_wh[256 * 128];                     // W_cat hi  [n][kp]
__device__ __align__(16) uint32_t g_wl[256 * 128];                     // W_cat lo
__device__ __align__(16) uint32_t g_wohi[128 * 128];                   // W_out hi  [n][kp]
__device__ __align__(16) uint32_t g_wolo[128 * 128];                   // W_out lo

// ---------------------------------------------------------------------------
// helpers
// ---------------------------------------------------------------------------
__device__ __forceinline__ uint32_t smem_u32(const void* p) {
    uint32_t a;
    asm("{ .reg .u64 t; cvta.to.shared.u64 t, %1; cvt.u32.u64 %0, t; }" : "=r"(a) : "l"(p));
    return a;
}
__device__ __forceinline__ void split2(float a0, float a1, uint32_t& hi, uint32_t& lo) {
    __nv_bfloat16 h0 = __float2bfloat16(a0), h1 = __float2bfloat16(a1);
    __nv_bfloat16 l0 = __float2bfloat16(a0 - __bfloat162float(h0));
    __nv_bfloat16 l1 = __float2bfloat16(a1 - __bfloat162float(h1));
    __nv_bfloat162 H; H.x = h0; H.y = h1;
    __nv_bfloat162 L; L.x = l0; L.y = l1;
    hi = *(uint32_t*)&H; lo = *(uint32_t*)&L;
}
__device__ __forceinline__ float gelu_exact(float t) {
    return 0.5f * t * (1.0f + erff(t * 0.70710678118654752f));
}

#define MMA(c, A0, A1, A2, A3, B0, B1)                                          \
    asm("mma.sync.aligned.m16n8k16.row.col.f32.bf16.bf16.f32 "                  \
        "{%0,%1,%2,%3},{%4,%5,%6,%7},{%8,%9},{%0,%1,%2,%3};"                    \
        : "+f"((c)[0]), "+f"((c)[1]), "+f"((c)[2]), "+f"((c)[3])                \
        : "r"(A0), "r"(A1), "r"(A2), "r"(A3), "r"(B0), "r"(B1))

#define LDSM4(R, addr)                                                          \
    asm volatile("ldmatrix.sync.aligned.m8n8.x4.shared.b16 {%0,%1,%2,%3}, [%4];"\
        : "=r"((R)[0]), "=r"((R)[1]), "=r"((R)[2]), "=r"((R)[3]) : "r"(addr))

#define CPA(dst, src, sz)                                                       \
    asm volatile("cp.async.ca.shared.global [%0], [%1], 16, %2;"                \
        :: "r"(dst), "l"(src), "r"(sz))
#define CPA16(dst, src)                                                         \
    asm volatile("cp.async.ca.shared.global [%0], [%1], 16;" :: "r"(dst), "l"(src))
#define CPCOMMIT() asm volatile("cp.async.commit_group;" ::: "memory")

// ---------------------------------------------------------------------------
// K0: zero degree counters
// ---------------------------------------------------------------------------
__global__ void zero_deg() {
    int i = blockIdx.x * 256 + threadIdx.x;
    if (i < NUM_DST) g_deg[i] = 0;
}

// ---------------------------------------------------------------------------
// K1: fill buckets — per edge: slot = atomicAdd(deg[dst]), bucket[dst][slot]=src
// ---------------------------------------------------------------------------
__global__ void fill_kernel(const int* __restrict__ esrc,
                            const int* __restrict__ edst) {
    int e = blockIdx.x * 256 + threadIdx.x;
    if (e >= NUM_EDGES) return;
    int s = __ldg(esrc + e);
    int d = __ldg(edst + e);
    int pos = atomicAdd(&g_deg[d], 1);
    if (pos < BUCKET_CAP)
        g_bucket[(size_t)d * BUCKET_CAP + pos] = s;
}

// ---------------------------------------------------------------------------
// K2: aggregate, column-split. Pass `half` covers x cols [half*64, half*64+64).
// ---------------------------------------------------------------------------
__global__ void agg_half(const float* __restrict__ x, int half) {
    int d    = blockIdx.x * 8 + (threadIdx.x >> 5);
    int lane = threadIdx.x & 31;
    if (d >= NUM_DST) return;

    int degT = g_deg[d];
    int deg  = min(degT, BUCKET_CAP);
    const int* lst = g_bucket + (size_t)d * BUCKET_CAP;
    const float2* x2 = (const float2*)x;       // row = 64 float2
    int off = half * 32 + lane;

    float s0 = 0.f, s1 = 0.f;
    int i = 0;
    for (; i + 8 <= deg; i += 8) {
        int e0 = __ldg(lst + i),     e1 = __ldg(lst + i + 1);
        int e2 = __ldg(lst + i + 2), e3 = __ldg(lst + i + 3);
        int e4 = __ldg(lst + i + 4), e5 = __ldg(lst + i + 5);
        int e6 = __ldg(lst + i + 6), e7 = __ldg(lst + i + 7);
        float2 v0 = __ldg(x2 + (size_t)e0 * 64 + off);
        float2 v1 = __ldg(x2 + (size_t)e1 * 64 + off);
        float2 v2 = __ldg(x2 + (size_t)e2 * 64 + off);
        float2 v3 = __ldg(x2 + (size_t)e3 * 64 + off);
        float2 v4 = __ldg(x2 + (size_t)e4 * 64 + off);
        float2 v5 = __ldg(x2 + (size_t)e5 * 64 + off);
        float2 v6 = __ldg(x2 + (size_t)e6 * 64 + off);
        float2 v7 = __ldg(x2 + (size_t)e7 * 64 + off);
        s0 += v0.x + v1.x + v2.x + v3.x + v4.x + v5.x + v6.x + v7.x;
        s1 += v0.y + v1.y + v2.y + v3.y + v4.y + v5.y + v6.y + v7.y;
    }
    for (; i + 4 <= deg; i += 4) {
        int e0 = __ldg(lst + i),     e1 = __ldg(lst + i + 1);
        int e2 = __ldg(lst + i + 2), e3 = __ldg(lst + i + 3);
        float2 v0 = __ldg(x2 + (size_t)e0 * 64 + off);
        float2 v1 = __ldg(x2 + (size_t)e1 * 64 + off);
        float2 v2 = __ldg(x2 + (size_t)e2 * 64 + off);
        float2 v3 = __ldg(x2 + (size_t)e3 * 64 + off);
        s0 += v0.x + v1.x + v2.x + v3.x;
        s1 += v0.y + v1.y + v2.y + v3.y;
    }
    for (; i < deg; ++i) {
        int e = __ldg(lst + i);
        float2 v = __ldg(x2 + (size_t)e * 64 + off);
        s0 += v.x; s1 += v.y;
    }

    float inv = 1.0f / fmaxf((float)degT, 1.0f);
    uint32_t hi, lo;
    split2(s0 * inv, s1 * inv, hi, lo);
    g_ah[(size_t)d * 128 + half * 32 + lane] = hi;
    g_al[(size_t)d * 128 + half * 32 + lane] = lo;

    float2 xv = __ldg(x2 + (size_t)d * 64 + off);
    split2(xv.x, xv.y, hi, lo);
    g_ah[(size_t)d * 128 + 64 + half * 32 + lane] = hi;
    g_al[(size_t)d * 128 + 64 + half * 32 + lane] = lo;
}

// ---------------------------------------------------------------------------
// K3: prep_w — split weights to bf16 hi/lo, [n][kp] layout.
// ---------------------------------------------------------------------------
__global__ void prep_w(const float* __restrict__ w_l,
                       const float* __restrict__ w_r,
                       const float* __restrict__ w_out) {
    int t = blockIdx.x * 256 + threadIdx.x;       // 0..49151
    if (t < 32768) {
        int kp = t >> 8, n = t & 255;
        int k0 = 2 * kp;
        float v0, v1;
        if (k0 < 128) { v0 = w_l[k0 * 256 + n];         v1 = w_l[(k0 + 1) * 256 + n]; }
        else          { v0 = w_r[(k0 - 128) * 256 + n]; v1 = w_r[(k0 - 127) * 256 + n]; }
        uint32_t hi, lo; split2(v0, v1, hi, lo);
        g_wh[n * 128 + kp] = hi; g_wl[n * 128 + kp] = lo;
    } else {
        int u = t - 32768;
        int kp = u >> 7, n = u & 127;
        int k0 = 2 * kp;
        float v0 = w_out[k0 * 128 + n], v1 = w_out[(k0 + 1) * 128 + n];
        uint32_t hi, lo; split2(v0, v1, hi, lo);
        g_wohi[n * 128 + kp] = hi; g_wolo[n * 128 + kp] = lo;
    }
}

// ---------------------------------------------------------------------------
// K4: fused — out = LN2( gelu(LN1(A@W_cat+b_l)) @ W_out + b_out )
// CTA 64 rows. Phase 1: N=256 gemm (warp tile 32x32, 16 warps 2m x 8n),
// cp.async double-buffered. Epilogue 1: LN1+GELU -> split-bf16 h in SMEM.
// Phase 2: N=128 gemm, A from smem h, W_out streamed double-buffered.
// Dynamic smem map (bytes):
//   phase 1 stages: s*81920 + {Ah@0(8K), Al@8192, Wh@16384(32K), Wl@49152}
//   phase 2:        sHh@0(32K), sHl@32768, Wout stage s: 65536+s*32768
//                   {Wh@0(16K), Wl@16384}
// ---------------------------------------------------------------------------
#define GF_SMEM 163840
__global__ __launch_bounds__(512, 1)
void fused_tc(const float* __restrict__ b_l,
              const float* __restrict__ ln1_g,
              const float* __restrict__ ln1_b,
              const float* __restrict__ b_out,
              const float* __restrict__ ln2_g,
              const float* __restrict__ ln2_b,
              float* __restrict__ out) {
    extern __shared__ uint32_t sm[];
    __shared__ float sSum[64][8], sSq[64][8];
    uint32_t sb = smem_u32(sm);

    int tid = threadIdx.x, wid = tid >> 5, lane = tid & 31;
    int wm = wid >> 3, wn = wid & 7;
    int g = lane >> 2, t4 = lane & 3;
    int row0 = blockIdx.x * 64;

    int ar = tid >> 3, ac = tid & 7;
    int agrow = row0 + ar;
    uint32_t asz = (agrow < NUM_DST) ? 16u : 0u;
    uint32_t adst = (uint32_t)(ar * 8 + (ac ^ (ar & 7))) * 16;
    const uint32_t* asrcH = g_ah + (size_t)agrow * 128 + ac * 4;
    const uint32_t* asrcL = g_al + (size_t)agrow * 128 + ac * 4;

    float acc[2][4][4];
#pragma unroll
    for (int mt = 0; mt < 2; ++mt)
#pragma unroll
        for (int nt = 0; nt < 4; ++nt)
#pragma unroll
            for (int j = 0; j < 4; ++j) acc[mt][nt][j] = 0.f;

#define P1_ISSUE(kc, s) do {                                                      \
        uint32_t base = sb + (s) * 81920;                                         \
        CPA(base + adst, asrcH + (kc) * 32, asz);                                 \
        CPA(base + 8192 + adst, asrcL + (kc) * 32, asz);                          \
        for (int i = tid; i < 2048; i += 512) {                                   \
            int n_ = i >> 3, c_ = i & 7;                                          \
            uint32_t d_ = base + 16384 + (uint32_t)(n_ * 8 + (c_ ^ (n_ & 7))) * 16;\
            CPA16(d_, g_wh + n_ * 128 + (kc) * 32 + c_ * 4);                      \
            CPA16(d_ + 32768, g_wl + n_ * 128 + (kc) * 32 + c_ * 4);              \
        }                                                                         \
        CPCOMMIT();                                                               \
    } while (0)

#define WOUT_ISSUE(kc, s) do {                                                    \
        uint32_t b2 = sb + 65536 + (s) * 32768;                                   \
        for (int i = tid; i < 1024; i += 512) {                                   \
            int n_ = i >> 3, c_ = i & 7;                                          \
            uint32_t d_ = b2 + (uint32_t)(n_ * 8 + (c_ ^ (n_ & 7))) * 16;         \
            CPA16(d_, g_wohi + n_ * 128 + (kc) * 32 + c_ * 4);                    \
            CPA16(d_ + 16384, g_wolo + n_ * 128 + (kc) * 32 + c_ * 4);            \
        }                                                                         \
        CPCOMMIT();                                                               \
    } while (0)

    P1_ISSUE(0, 0);

    int arow = (lane & 15);
    int asel = lane >> 4;
    int wrow = ((lane >> 4) << 3) + (lane & 7);
    int wsel = (lane >> 3) & 1;

    // ================= Phase 1 mainloop =================
    for (int kc = 0; kc < 4; ++kc) {
        if (kc < 3) {
            P1_ISSUE(kc + 1, (kc + 1) & 1);
            asm volatile("cp.async.wait_group 1;" ::: "memory");
        } else {
            asm volatile("cp.async.wait_group 0;" ::: "memory");
        }
        __syncthreads();
        uint32_t base = sb + (kc & 1) * 81920;

#pragma unroll
        for (int ks = 0; ks < 4; ++ks) {
            uint32_t a_h[2][4], a_l[2][4], b_h[2][4], b_l2[2][4];
#pragma unroll
            for (int mt = 0; mt < 2; ++mt) {
                int r = wm * 32 + mt * 16 + arow;
                uint32_t ad = base + (uint32_t)(r * 8 + ((2 * ks + asel) ^ (r & 7))) * 16;
                LDSM4(a_h[mt], ad);
                LDSM4(a_l[mt], ad + 8192);
            }
#pragma unroll
            for (int ntp = 0; ntp < 2; ++ntp) {
                int n_ = wn * 32 + ntp * 16 + wrow;
                uint32_t wd = base + 16384 + (uint32_t)(n_ * 8 + ((2 * ks + wsel) ^ (n_ & 7))) * 16;
                LDSM4(b_h[ntp], wd);
                LDSM4(b_l2[ntp], wd + 32768);
            }
#pragma unroll
            for (int nt = 0; nt < 4; ++nt) {
                uint32_t bh0 = b_h[nt >> 1][(nt & 1) * 2], bh1 = b_h[nt >> 1][(nt & 1) * 2 + 1];
                uint32_t bl0 = b_l2[nt >> 1][(nt & 1) * 2], bl1 = b_l2[nt >> 1][(nt & 1) * 2 + 1];
#pragma unroll
                for (int mt = 0; mt < 2; ++mt) {
                    MMA(acc[mt][nt], a_h[mt][0], a_h[mt][1], a_h[mt][2], a_h[mt][3], bh0, bh1);
                    MMA(acc[mt][nt], a_h[mt][0], a_h[mt][1], a_h[mt][2], a_h[mt][3], bl0, bl1);
                    MMA(acc[mt][nt], a_l[mt][0], a_l[mt][1], a_l[mt][2], a_l[mt][3], bh0, bh1);
                }
            }
        }
        __syncthreads();
    }

    // W_out chunk 0 in flight while epilogue 1 computes
    WOUT_ISSUE(0, 0);

    // ================= Epilogue 1: bias + LN1 + GELU -> smem h =================
#pragma unroll
    for (int nt = 0; nt < 4; ++nt) {
        int col = wn * 32 + nt * 8 + t4 * 2;
        float b0 = __ldg(b_l + col), b1 = __ldg(b_l + col + 1);
#pragma unroll
        for (int mt = 0; mt < 2; ++mt) {
            acc[mt][nt][0] += b0; acc[mt][nt][1] += b1;
            acc[mt][nt][2] += b0; acc[mt][nt][3] += b1;
        }
    }
#pragma unroll
    for (int mt = 0; mt < 2; ++mt)
#pragma unroll
        for (int ro = 0; ro < 2; ++ro) {
            float s = 0.f, q = 0.f;
#pragma unroll
            for (int nt = 0; nt < 4; ++nt) {
                float c0 = acc[mt][nt][ro * 2], c1 = acc[mt][nt][ro * 2 + 1];
                s += c0 + c1; q += c0 * c0 + c1 * c1;
            }
            s += __shfl_xor_sync(0xffffffffu, s, 1); q += __shfl_xor_sync(0xffffffffu, q, 1);
            s += __shfl_xor_sync(0xffffffffu, s, 2); q += __shfl_xor_sync(0xffffffffu, q, 2);
            if (t4 == 0) {
                int r = wm * 32 + mt * 16 + ro * 8 + g;
                sSum[r][wn] = s; sSq[r][wn] = q;
            }
        }
    __syncthreads();

#pragma unroll
    for (int mt = 0; mt < 2; ++mt)
#pragma unroll
        for (int ro = 0; ro < 2; ++ro) {
            int r = wm * 32 + mt * 16 + ro * 8 + g;
            float S = 0.f, SQ = 0.f;
#pragma unroll
            for (int j = 0; j < 8; ++j) { S += sSum[r][j]; SQ += sSq[r][j]; }
            float mu   = S * (1.0f / HID);
            float var  = SQ * (1.0f / HID) - mu * mu;
            float rstd = rsqrtf(var + 1e-5f);
#pragma unroll
            for (int nt = 0; nt < 4; ++nt) {
                int col = wn * 32 + nt * 8 + t4 * 2;
                float c0 = acc[mt][nt][ro * 2], c1 = acc[mt][nt][ro * 2 + 1];
                float v0 = gelu_exact((c0 - mu) * rstd * __ldg(ln1_g + col)     + __ldg(ln1_b + col));
                float v1 = gelu_exact((c1 - mu) * rstd * __ldg(ln1_g + col + 1) + __ldg(ln1_b + col + 1));
                uint32_t hi, lo; split2(v0, v1, hi, lo);
                int kp = col >> 1;                       // 0..127
                uint32_t off = (uint32_t)(r * 32 + ((kp >> 2) ^ (r & 7))) * 16 + (kp & 3) * 4;
                *(uint32_t*)((char*)sm + off)         = hi;
                *(uint32_t*)((char*)sm + 32768 + off) = lo;
            }
        }
    __syncthreads();

    // ================= Phase 2: out-gemm, A from smem h =================
    float acc2[2][2][4];
#pragma unroll
    for (int mt = 0; mt < 2; ++mt)
#pragma unroll
        for (int nt = 0; nt < 2; ++nt)
#pragma unroll
            for (int j = 0; j < 4; ++j) acc2[mt][nt][j] = 0.f;

    for (int kc = 0; kc < 4; ++kc) {
        if (kc < 3) {
            WOUT_ISSUE(kc + 1, (kc + 1) & 1);
            asm volatile("cp.async.wait_group 1;" ::: "memory");
        } else {
            asm volatile("cp.async.wait_group 0;" ::: "memory");
        }
        __syncthreads();
        uint32_t b2 = sb + 65536 + (kc & 1) * 32768;

#pragma unroll
        for (int ks = 0; ks < 4; ++ks) {
            uint32_t a_h[2][4], a_l[2][4], b_h[4], b_l2[4];
#pragma unroll
            for (int mt = 0; mt < 2; ++mt) {
                int r = wm * 32 + mt * 16 + arow;
                uint32_t ad = sb + (uint32_t)(r * 32 + ((kc * 8 + 2 * ks + asel) ^ (r & 7))) * 16;
                LDSM4(a_h[mt], ad);
                LDSM4(a_l[mt], ad + 32768);
            }
            {
                int n_ = wn * 16 + wrow;
                uint32_t wd = b2 + (uint32_t)(n_ * 8 + ((2 * ks + wsel) ^ (n_ & 7))) * 16;
                LDSM4(b_h, wd);
                LDSM4(b_l2, wd + 16384);
            }
#pragma unroll
            for (int nt = 0; nt < 2; ++nt) {
                uint32_t bh0 = b_h[nt * 2], bh1 = b_h[nt * 2 + 1];
                uint32_t bl0 = b_l2[nt * 2], bl1 = b_l2[nt * 2 + 1];
#pragma unroll
                for (int mt = 0; mt < 2; ++mt) {
                    MMA(acc2[mt][nt], a_h[mt][0], a_h[mt][1], a_h[mt][2], a_h[mt][3], bh0, bh1);
                    MMA(acc2[mt][nt], a_h[mt][0], a_h[mt][1], a_h[mt][2], a_h[mt][3], bl0, bl1);
                    MMA(acc2[mt][nt], a_l[mt][0], a_l[mt][1], a_l[mt][2], a_l[mt][3], bh0, bh1);
                }
            }
        }
        __syncthreads();
    }

    // ================= Epilogue 2: bias + LN2 -> out =================
#pragma unroll
    for (int nt = 0; nt < 2; ++nt) {
        int col = wn * 16 + nt * 8 + t4 * 2;
        float b0 = __ldg(b_out + col), b1 = __ldg(b_out + col + 1);
#pragma unroll
        for (int mt = 0; mt < 2; ++mt) {
            acc2[mt][nt][0] += b0; acc2[mt][nt][1] += b1;
            acc2[mt][nt][2] += b0; acc2[mt][nt][3] += b1;
        }
    }
#pragma unroll
    for (int mt = 0; mt < 2; ++mt)
#pragma unroll
        for (int ro = 0; ro < 2; ++ro) {
            float s = 0.f, q = 0.f;
#pragma unroll
            for (int nt = 0; nt < 2; ++nt) {
                float c0 = acc2[mt][nt][ro * 2], c1 = acc2[mt][nt][ro * 2 + 1];
                s += c0 + c1; q += c0 * c0 + c1 * c1;
            }
            s += __shfl_xor_sync(0xffffffffu, s, 1); q += __shfl_xor_sync(0xffffffffu, q, 1);
            s += __shfl_xor_sync(0xffffffffu, s, 2); q += __shfl_xor_sync(0xffffffffu, q, 2);
            if (t4 == 0) {
                int r = wm * 32 + mt * 16 + ro * 8 + g;
                sSum[r][wn] = s; sSq[r][wn] = q;
            }
        }
    __syncthreads();

#pragma unroll
    for (int mt = 0; mt < 2; ++mt)
#pragma unroll
        for (int ro = 0; ro < 2; ++ro) {
            int r = wm * 32 + mt * 16 + ro * 8 + g;
            int grow = row0 + r;
            float S = 0.f, SQ = 0.f;
#pragma unroll
            for (int j = 0; j < 8; ++j) { S += sSum[r][j]; SQ += sSq[r][j]; }
            float mu   = S * (1.0f / OUT_DIM);
            float var  = SQ * (1.0f / OUT_DIM) - mu * mu;
            float rstd = rsqrtf(var + 1e-5f);
            if (grow >= NUM_DST) continue;
#pragma unroll
            for (int nt = 0; nt < 2; ++nt) {
                int col = wn * 16 + nt * 8 + t4 * 2;
                float c0 = acc2[mt][nt][ro * 2], c1 = acc2[mt][nt][ro * 2 + 1];
                float2 o;
                o.x = (c0 - mu) * rstd * __ldg(ln2_g + col)     + __ldg(ln2_b + col);
                o.y = (c1 - mu) * rstd * __ldg(ln2_g + col + 1) + __ldg(ln2_b + col + 1);
                *(float2*)(out + (size_t)grow * 128 + col) = o;
            }
        }
}

// ---------------------------------------------------------------------------
extern "C" void kernel_launch(void* const* d_in, const int* in_sizes, int n_in,
                              void* d_out, int out_size) {
    const float* x     = (const float*)d_in[0];
    const float* w_l   = (const float*)d_in[1];
    const float* b_l   = (const float*)d_in[2];
    const float* w_r   = (const float*)d_in[3];
    const float* ln1_g = (const float*)d_in[4];
    const float* ln1_b = (const float*)d_in[5];
    const float* w_out = (const float*)d_in[6];
    const float* b_out = (const float*)d_in[7];
    const float* ln2_g = (const float*)d_in[8];
    const float* ln2_b = (const float*)d_in[9];
    const int*   esrc  = (const int*)d_in[10];
    const int*   edst  = (const int*)d_in[11];
    float* out = (float*)d_out;

    cudaFuncSetAttribute(fused_tc, cudaFuncAttributeMaxDynamicSharedMemorySize, GF_SMEM);

    zero_deg<<<(NUM_DST + 255) / 256, 256>>>();
    fill_kernel<<<(NUM_EDGES + 255) / 256, 256>>>(esrc, edst);
    prep_w<<<192, 256>>>(w_l, w_r, w_out);
    agg_half<<<(NUM_DST + 7) / 8, 256>>>(x, 0);
    agg_half<<<(NUM_DST + 7) / 8, 256>>>(x, 1);

    fused_tc<<<NRB, 512, GF_SMEM>>>(b_l, ln1_g, ln1_b, b_out, ln2_g, ln2_b, out);
}

// round 12
// speedup vs baseline: 1.5669x; 1.0398x over previous
#include <cuda_runtime.h>
#include <cuda_bf16.h>
#include <math.h>
#include <stdint.h>

#define NUM_SRC   200000
#define NUM_DST   100000
#define NUM_EDGES 1600000
#define IN_DIM    128
#define HID       256
#define OUT_DIM   128
#define NRB2      782       // ceil(NUM_DST/128)
#define BUCKET_CAP 64

// ---------------------------------------------------------------------------
// Scratch (__device__ globals; no allocation allowed)
// ---------------------------------------------------------------------------
__device__ __align__(16) int      g_deg[NUM_DST];
__device__ __align__(16) int      g_bucket[(size_t)NUM_DST * BUCKET_CAP];
__device__ __align__(16) uint32_t g_ah[(size_t)NUM_DST * 128];
__device__ __align__(16) uint32_t g_al[(size_t)NUM_DST * 128];
__device__ __align__(16) uint32_t g_wh[256 * 128];
__device__ __align__(16) uint32_t g_wl[256 * 128];
__device__ __align__(16) uint32_t g_wohi[128 * 128];
__device__ __align__(16) uint32_t g_wolo[128 * 128];

// ---------------------------------------------------------------------------
// helpers
// ---------------------------------------------------------------------------
__device__ __forceinline__ uint32_t smem_u32(const void* p) {
    uint32_t a;
    asm("{ .reg .u64 t; cvta.to.shared.u64 t, %1; cvt.u32.u64 %0, t; }" : "=r"(a) : "l"(p));
    return a;
}
__device__ __forceinline__ void split2(float a0, float a1, uint32_t& hi, uint32_t& lo) {
    __nv_bfloat16 h0 = __float2bfloat16(a0), h1 = __float2bfloat16(a1);
    __nv_bfloat16 l0 = __float2bfloat16(a0 - __bfloat162float(h0));
    __nv_bfloat16 l1 = __float2bfloat16(a1 - __bfloat162float(h1));
    __nv_bfloat162 H; H.x = h0; H.y = h1;
    __nv_bfloat162 L; L.x = l0; L.y = l1;
    hi = *(uint32_t*)&H; lo = *(uint32_t*)&L;
}
__device__ __forceinline__ float gelu_exact(float t) {
    return 0.5f * t * (1.0f + erff(t * 0.70710678118654752f));
}

#define MMA(c, A0, A1, A2, A3, B0, B1)                                          \
    asm("mma.sync.aligned.m16n8k16.row.col.f32.bf16.bf16.f32 "                  \
        "{%0,%1,%2,%3},{%4,%5,%6,%7},{%8,%9},{%0,%1,%2,%3};"                    \
        : "+f"((c)[0]), "+f"((c)[1]), "+f"((c)[2]), "+f"((c)[3])                \
        : "r"(A0), "r"(A1), "r"(A2), "r"(A3), "r"(B0), "r"(B1))

#define LDSM4(R, addr)                                                          \
    asm volatile("ldmatrix.sync.aligned.m8n8.x4.shared.b16 {%0,%1,%2,%3}, [%4];"\
        : "=r"((R)[0]), "=r"((R)[1]), "=r"((R)[2]), "=r"((R)[3]) : "r"(addr))

#define CPA(dst, src, sz)                                                       \
    asm volatile("cp.async.ca.shared.global [%0], [%1], 16, %2;"                \
        :: "r"(dst), "l"(src), "r"(sz))
#define CPA16(dst, src)                                                         \
    asm volatile("cp.async.ca.shared.global [%0], [%1], 16;" :: "r"(dst), "l"(src))
#define CPCOMMIT() asm volatile("cp.async.commit_group;" ::: "memory")

// ---------------------------------------------------------------------------
__global__ void zero_deg() {
    int i = blockIdx.x * 256 + threadIdx.x;
    if (i < NUM_DST) g_deg[i] = 0;
}

__global__ void fill_kernel(const int* __restrict__ esrc,
                            const int* __restrict__ edst) {
    int e = blockIdx.x * 256 + threadIdx.x;
    if (e >= NUM_EDGES) return;
    int s = __ldg(esrc + e);
    int d = __ldg(edst + e);
    int pos = atomicAdd(&g_deg[d], 1);
    if (pos < BUCKET_CAP)
        g_bucket[(size_t)d * BUCKET_CAP + pos] = s;
}

// ---------------------------------------------------------------------------
// aggregate, column-split (unchanged from R10/R11 winner)
// ---------------------------------------------------------------------------
__global__ void agg_half(const float* __restrict__ x, int half) {
    int d    = blockIdx.x * 8 + (threadIdx.x >> 5);
    int lane = threadIdx.x & 31;
    if (d >= NUM_DST) return;

    int degT = g_deg[d];
    int deg  = min(degT, BUCKET_CAP);
    const int* lst = g_bucket + (size_t)d * BUCKET_CAP;
    const float2* x2 = (const float2*)x;
    int off = half * 32 + lane;

    float s0 = 0.f, s1 = 0.f;
    int i = 0;
    for (; i + 8 <= deg; i += 8) {
        int e0 = __ldg(lst + i),     e1 = __ldg(lst + i + 1);
        int e2 = __ldg(lst + i + 2), e3 = __ldg(lst + i + 3);
        int e4 = __ldg(lst + i + 4), e5 = __ldg(lst + i + 5);
        int e6 = __ldg(lst + i + 6), e7 = __ldg(lst + i + 7);
        float2 v0 = __ldg(x2 + (size_t)e0 * 64 + off);
        float2 v1 = __ldg(x2 + (size_t)e1 * 64 + off);
        float2 v2 = __ldg(x2 + (size_t)e2 * 64 + off);
        float2 v3 = __ldg(x2 + (size_t)e3 * 64 + off);
        float2 v4 = __ldg(x2 + (size_t)e4 * 64 + off);
        float2 v5 = __ldg(x2 + (size_t)e5 * 64 + off);
        float2 v6 = __ldg(x2 + (size_t)e6 * 64 + off);
        float2 v7 = __ldg(x2 + (size_t)e7 * 64 + off);
        s0 += v0.x + v1.x + v2.x + v3.x + v4.x + v5.x + v6.x + v7.x;
        s1 += v0.y + v1.y + v2.y + v3.y + v4.y + v5.y + v6.y + v7.y;
    }
    for (; i + 4 <= deg; i += 4) {
        int e0 = __ldg(lst + i),     e1 = __ldg(lst + i + 1);
        int e2 = __ldg(lst + i + 2), e3 = __ldg(lst + i + 3);
        float2 v0 = __ldg(x2 + (size_t)e0 * 64 + off);
        float2 v1 = __ldg(x2 + (size_t)e1 * 64 + off);
        float2 v2 = __ldg(x2 + (size_t)e2 * 64 + off);
        float2 v3 = __ldg(x2 + (size_t)e3 * 64 + off);
        s0 += v0.x + v1.x + v2.x + v3.x;
        s1 += v0.y + v1.y + v2.y + v3.y;
    }
    for (; i < deg; ++i) {
        int e = __ldg(lst + i);
        float2 v = __ldg(x2 + (size_t)e * 64 + off);
        s0 += v.x; s1 += v.y;
    }

    float inv = 1.0f / fmaxf((float)degT, 1.0f);
    uint32_t hi, lo;
    split2(s0 * inv, s1 * inv, hi, lo);
    g_ah[(size_t)d * 128 + half * 32 + lane] = hi;
    g_al[(size_t)d * 128 + half * 32 + lane] = lo;

    float2 xv = __ldg(x2 + (size_t)d * 64 + off);
    split2(xv.x, xv.y, hi, lo);
    g_ah[(size_t)d * 128 + 64 + half * 32 + lane] = hi;
    g_al[(size_t)d * 128 + 64 + half * 32 + lane] = lo;
}

// ---------------------------------------------------------------------------
// prep_w (unchanged)
// ---------------------------------------------------------------------------
__global__ void prep_w(const float* __restrict__ w_l,
                       const float* __restrict__ w_r,
                       const float* __restrict__ w_out) {
    int t = blockIdx.x * 256 + threadIdx.x;
    if (t < 32768) {
        int kp = t >> 8, n = t & 255;
        int k0 = 2 * kp;
        float v0, v1;
        if (k0 < 128) { v0 = w_l[k0 * 256 + n];         v1 = w_l[(k0 + 1) * 256 + n]; }
        else          { v0 = w_r[(k0 - 128) * 256 + n]; v1 = w_r[(k0 - 127) * 256 + n]; }
        uint32_t hi, lo; split2(v0, v1, hi, lo);
        g_wh[n * 128 + kp] = hi; g_wl[n * 128 + kp] = lo;
    } else {
        int u = t - 32768;
        int kp = u >> 7, n = u & 127;
        int k0 = 2 * kp;
        float v0 = w_out[k0 * 128 + n], v1 = w_out[(k0 + 1) * 128 + n];
        uint32_t hi, lo; split2(v0, v1, hi, lo);
        g_wohi[n * 128 + kp] = hi; g_wolo[n * 128 + kp] = lo;
    }
}

// ---------------------------------------------------------------------------
// fused, M=128 per CTA.
// Phase 1: 128x256 gemm, 16 warps 4m x 4n (warp tile 32x64), K=256 in 4 chunks.
// Phase 2: 128x128 gemm from smem h, warps 4m x 4n (warp tile 32x32).
// smem (bytes):
//   phase1 stage s @ s*98304: Ah 16K@0, Al 16K@16384, Wh 32K@32768, Wl 32K@65536
//   phase2: hHi 64K@0, hLo 64K@65536, Wout stage s @ 131072+s*32768 (hi 16K, lo 16K)
// Total 196608.
// ---------------------------------------------------------------------------
#define GF_SMEM 196608
__global__ __launch_bounds__(512, 1)
void fused_tc(const float* __restrict__ b_l,
              const float* __restrict__ ln1_g,
              const float* __restrict__ ln1_b,
              const float* __restrict__ b_out,
              const float* __restrict__ ln2_g,
              const float* __restrict__ ln2_b,
              float* __restrict__ out) {
    extern __shared__ uint32_t sm[];
    __shared__ float sSum[128][4], sSq[128][4];
    uint32_t sb = smem_u32(sm);

    int tid = threadIdx.x, wid = tid >> 5, lane = tid & 31;
    int wm = wid >> 2, wn = wid & 3;          // 4m x 4n
    int g = lane >> 2, t4 = lane & 3;
    int row0 = blockIdx.x * 128;

    float acc[2][8][4];
#pragma unroll
    for (int mt = 0; mt < 2; ++mt)
#pragma unroll
        for (int nt = 0; nt < 8; ++nt)
#pragma unroll
            for (int j = 0; j < 4; ++j) acc[mt][nt][j] = 0.f;

#define P1_ISSUE(kc, s) do {                                                      \
        uint32_t base = sb + (s) * 98304;                                         \
        for (int i = tid; i < 1024; i += 512) {                                   \
            int r_ = i >> 3, c_ = i & 7;                                          \
            int grow_ = row0 + r_;                                                \
            uint32_t sz_ = (grow_ < NUM_DST) ? 16u : 0u;                          \
            uint32_t d_ = base + (uint32_t)(r_ * 8 + (c_ ^ (r_ & 7))) * 16;       \
            CPA(d_,         g_ah + (size_t)grow_ * 128 + (kc) * 32 + c_ * 4, sz_);\
            CPA(d_ + 16384, g_al + (size_t)grow_ * 128 + (kc) * 32 + c_ * 4, sz_);\
        }                                                                         \
        for (int i = tid; i < 2048; i += 512) {                                   \
            int n_ = i >> 3, c_ = i & 7;                                          \
            uint32_t d_ = base + 32768 + (uint32_t)(n_ * 8 + (c_ ^ (n_ & 7))) * 16;\
            CPA16(d_, g_wh + n_ * 128 + (kc) * 32 + c_ * 4);                      \
            CPA16(d_ + 32768, g_wl + n_ * 128 + (kc) * 32 + c_ * 4);              \
        }                                                                         \
        CPCOMMIT();                                                               \
    } while (0)

#define WOUT_ISSUE(kc, s) do {                                                    \
        uint32_t b2 = sb + 131072 + (s) * 32768;                                  \
        for (int i = tid; i < 1024; i += 512) {                                   \
            int n_ = i >> 3, c_ = i & 7;                                          \
            uint32_t d_ = b2 + (uint32_t)(n_ * 8 + (c_ ^ (n_ & 7))) * 16;         \
            CPA16(d_, g_wohi + n_ * 128 + (kc) * 32 + c_ * 4);                    \
            CPA16(d_ + 16384, g_wolo + n_ * 128 + (kc) * 32 + c_ * 4);            \
        }                                                                         \
        CPCOMMIT();                                                               \
    } while (0)

    P1_ISSUE(0, 0);

    int arow = (lane & 15);
    int asel = lane >> 4;
    int wrow = ((lane >> 4) << 3) + (lane & 7);
    int wsel = (lane >> 3) & 1;

    // ================= Phase 1 mainloop =================
    for (int kc = 0; kc < 4; ++kc) {
        if (kc < 3) {
            P1_ISSUE(kc + 1, (kc + 1) & 1);
            asm volatile("cp.async.wait_group 1;" ::: "memory");
        } else {
            asm volatile("cp.async.wait_group 0;" ::: "memory");
        }
        __syncthreads();
        uint32_t base = sb + (kc & 1) * 98304;

#pragma unroll
        for (int ks = 0; ks < 4; ++ks) {
            uint32_t a_h[2][4], a_l[2][4];
#pragma unroll
            for (int mt = 0; mt < 2; ++mt) {
                int r = wm * 32 + mt * 16 + arow;
                uint32_t ad = base + (uint32_t)(r * 8 + ((2 * ks + asel) ^ (r & 7))) * 16;
                LDSM4(a_h[mt], ad);
                LDSM4(a_l[mt], ad + 16384);
            }
#pragma unroll
            for (int ntp = 0; ntp < 4; ++ntp) {
                uint32_t b_h[4], b_l2[4];
                int n_ = wn * 64 + ntp * 16 + wrow;
                uint32_t wd = base + 32768 + (uint32_t)(n_ * 8 + ((2 * ks + wsel) ^ (n_ & 7))) * 16;
                LDSM4(b_h, wd);
                LDSM4(b_l2, wd + 32768);
#pragma unroll
                for (int sub = 0; sub < 2; ++sub) {
                    int nt = ntp * 2 + sub;
                    uint32_t bh0 = b_h[sub * 2], bh1 = b_h[sub * 2 + 1];
                    uint32_t bl0 = b_l2[sub * 2], bl1 = b_l2[sub * 2 + 1];
#pragma unroll
                    for (int mt = 0; mt < 2; ++mt) {
                        MMA(acc[mt][nt], a_h[mt][0], a_h[mt][1], a_h[mt][2], a_h[mt][3], bh0, bh1);
                        MMA(acc[mt][nt], a_h[mt][0], a_h[mt][1], a_h[mt][2], a_h[mt][3], bl0, bl1);
                        MMA(acc[mt][nt], a_l[mt][0], a_l[mt][1], a_l[mt][2], a_l[mt][3], bh0, bh1);
                    }
                }
            }
        }
        __syncthreads();
    }

    WOUT_ISSUE(0, 0);

    // ================= Epilogue 1: bias + LN1 + GELU -> smem h =================
#pragma unroll
    for (int nt = 0; nt < 8; ++nt) {
        int col = wn * 64 + nt * 8 + t4 * 2;
        float b0 = __ldg(b_l + col), b1 = __ldg(b_l + col + 1);
#pragma unroll
        for (int mt = 0; mt < 2; ++mt) {
            acc[mt][nt][0] += b0; acc[mt][nt][1] += b1;
            acc[mt][nt][2] += b0; acc[mt][nt][3] += b1;
        }
    }
#pragma unroll
    for (int mt = 0; mt < 2; ++mt)
#pragma unroll
        for (int ro = 0; ro < 2; ++ro) {
            float s = 0.f, q = 0.f;
#pragma unroll
            for (int nt = 0; nt < 8; ++nt) {
                float c0 = acc[mt][nt][ro * 2], c1 = acc[mt][nt][ro * 2 + 1];
                s += c0 + c1; q += c0 * c0 + c1 * c1;
            }
            s += __shfl_xor_sync(0xffffffffu, s, 1); q += __shfl_xor_sync(0xffffffffu, q, 1);
            s += __shfl_xor_sync(0xffffffffu, s, 2); q += __shfl_xor_sync(0xffffffffu, q, 2);
            if (t4 == 0) {
                int r = wm * 32 + mt * 16 + ro * 8 + g;
                sSum[r][wn] = s; sSq[r][wn] = q;
            }
        }
    __syncthreads();

#pragma unroll
    for (int mt = 0; mt < 2; ++mt)
#pragma unroll
        for (int ro = 0; ro < 2; ++ro) {
            int r = wm * 32 + mt * 16 + ro * 8 + g;
            float S = sSum[r][0] + sSum[r][1] + sSum[r][2] + sSum[r][3];
            float SQ = sSq[r][0] + sSq[r][1] + sSq[r][2] + sSq[r][3];
            float mu   = S * (1.0f / HID);
            float var  = SQ * (1.0f / HID) - mu * mu;
            float rstd = rsqrtf(var + 1e-5f);
#pragma unroll
            for (int nt = 0; nt < 8; ++nt) {
                int col = wn * 64 + nt * 8 + t4 * 2;
                float c0 = acc[mt][nt][ro * 2], c1 = acc[mt][nt][ro * 2 + 1];
                float v0 = gelu_exact((c0 - mu) * rstd * __ldg(ln1_g + col)     + __ldg(ln1_b + col));
                float v1 = gelu_exact((c1 - mu) * rstd * __ldg(ln1_g + col + 1) + __ldg(ln1_b + col + 1));
                uint32_t hi, lo; split2(v0, v1, hi, lo);
                int kp = col >> 1;
                uint32_t off = (uint32_t)(r * 32 + ((kp >> 2) ^ (r & 7))) * 16 + (kp & 3) * 4;
                *(uint32_t*)((char*)sm + off)         = hi;
                *(uint32_t*)((char*)sm + 65536 + off) = lo;
            }
        }
    __syncthreads();

    // ================= Phase 2: out-gemm, A from smem h =================
    float acc2[2][4][4];
#pragma unroll
    for (int mt = 0; mt < 2; ++mt)
#pragma unroll
        for (int nt = 0; nt < 4; ++nt)
#pragma unroll
            for (int j = 0; j < 4; ++j) acc2[mt][nt][j] = 0.f;

    for (int kc = 0; kc < 4; ++kc) {
        if (kc < 3) {
            WOUT_ISSUE(kc + 1, (kc + 1) & 1);
            asm volatile("cp.async.wait_group 1;" ::: "memory");
        } else {
            asm volatile("cp.async.wait_group 0;" ::: "memory");
        }
        __syncthreads();
        uint32_t b2 = sb + 131072 + (kc & 1) * 32768;

#pragma unroll
        for (int ks = 0; ks < 4; ++ks) {
            uint32_t a_h[2][4], a_l[2][4];
#pragma unroll
            for (int mt = 0; mt < 2; ++mt) {
                int r = wm * 32 + mt * 16 + arow;
                uint32_t ad = sb + (uint32_t)(r * 32 + ((kc * 8 + 2 * ks + asel) ^ (r & 7))) * 16;
                LDSM4(a_h[mt], ad);
                LDSM4(a_l[mt], ad + 65536);
            }
#pragma unroll
            for (int ntp = 0; ntp < 2; ++ntp) {
                uint32_t b_h[4], b_l2[4];
                int n_ = wn * 32 + ntp * 16 + wrow;
                uint32_t wd = b2 + (uint32_t)(n_ * 8 + ((2 * ks + wsel) ^ (n_ & 7))) * 16;
                LDSM4(b_h, wd);
                LDSM4(b_l2, wd + 16384);
#pragma unroll
                for (int sub = 0; sub < 2; ++sub) {
                    int nt = ntp * 2 + sub;
                    uint32_t bh0 = b_h[sub * 2], bh1 = b_h[sub * 2 + 1];
                    uint32_t bl0 = b_l2[sub * 2], bl1 = b_l2[sub * 2 + 1];
#pragma unroll
                    for (int mt = 0; mt < 2; ++mt) {
                        MMA(acc2[mt][nt], a_h[mt][0], a_h[mt][1], a_h[mt][2], a_h[mt][3], bh0, bh1);
                        MMA(acc2[mt][nt], a_h[mt][0], a_h[mt][1], a_h[mt][2], a_h[mt][3], bl0, bl1);
                        MMA(acc2[mt][nt], a_l[mt][0], a_l[mt][1], a_l[mt][2], a_l[mt][3], bh0, bh1);
                    }
                }
            }
        }
        __syncthreads();
    }

    // ================= Epilogue 2: bias + LN2 -> out =================
#pragma unroll
    for (int nt = 0; nt < 4; ++nt) {
        int col = wn * 32 + nt * 8 + t4 * 2;
        float b0 = __ldg(b_out + col), b1 = __ldg(b_out + col + 1);
#pragma unroll
        for (int mt = 0; mt < 2; ++mt) {
            acc2[mt][nt][0] += b0; acc2[mt][nt][1] += b1;
            acc2[mt][nt][2] += b0; acc2[mt][nt][3] += b1;
        }
    }
#pragma unroll
    for (int mt = 0; mt < 2; ++mt)
#pragma unroll
        for (int ro = 0; ro < 2; ++ro) {
            float s = 0.f, q = 0.f;
#pragma unroll
            for (int nt = 0; nt < 4; ++nt) {
                float c0 = acc2[mt][nt][ro * 2], c1 = acc2[mt][nt][ro * 2 + 1];
                s += c0 + c1; q += c0 * c0 + c1 * c1;
            }
            s += __shfl_xor_sync(0xffffffffu, s, 1); q += __shfl_xor_sync(0xffffffffu, q, 1);
            s += __shfl_xor_sync(0xffffffffu, s, 2); q += __shfl_xor_sync(0xffffffffu, q, 2);
            if (t4 == 0) {
                int r = wm * 32 + mt * 16 + ro * 8 + g;
                sSum[r][wn] = s; sSq[r][wn] = q;
            }
        }
    __syncthreads();

#pragma unroll
    for (int mt = 0; mt < 2; ++mt)
#pragma unroll
        for (int ro = 0; ro < 2; ++ro) {
            int r = wm * 32 + mt * 16 + ro * 8 + g;
            int grow = row0 + r;
            float S = sSum[r][0] + sSum[r][1] + sSum[r][2] + sSum[r][3];
            float SQ = sSq[r][0] + sSq[r][1] + sSq[r][2] + sSq[r][3];
            float mu   = S * (1.0f / OUT_DIM);
            float var  = SQ * (1.0f / OUT_DIM) - mu * mu;
            float rstd = rsqrtf(var + 1e-5f);
            if (grow >= NUM_DST) continue;
#pragma unroll
            for (int nt = 0; nt < 4; ++nt) {
                int col = wn * 32 + nt * 8 + t4 * 2;
                float c0 = acc2[mt][nt][ro * 2], c1 = acc2[mt][nt][ro * 2 + 1];
                float2 o;
                o.x = (c0 - mu) * rstd * __ldg(ln2_g + col)     + __ldg(ln2_b + col);
                o.y = (c1 - mu) * rstd * __ldg(ln2_g + col + 1) + __ldg(ln2_b + col + 1);
                *(float2*)(out + (size_t)grow * 128 + col) = o;
            }
        }
}

// ---------------------------------------------------------------------------
extern "C" void kernel_launch(void* const* d_in, const int* in_sizes, int n_in,
                              void* d_out, int out_size) {
    const float* x     = (const float*)d_in[0];
    const float* w_l   = (const float*)d_in[1];
    const float* b_l   = (const float*)d_in[2];
    const float* w_r   = (const float*)d_in[3];
    const float* ln1_g = (const float*)d_in[4];
    const float* ln1_b = (const float*)d_in[5];
    const float* w_out = (const float*)d_in[6];
    const float* b_out = (const float*)d_in[7];
    const float* ln2_g = (const float*)d_in[8];
    const float* ln2_b = (const float*)d_in[9];
    const int*   esrc  = (const int*)d_in[10];
    const int*   edst  = (const int*)d_in[11];
    float* out = (float*)d_out;

    cudaFuncSetAttribute(fused_tc, cudaFuncAttributeMaxDynamicSharedMemorySize, GF_SMEM);

    zero_deg<<<(NUM_DST + 255) / 256, 256>>>();
    fill_kernel<<<(NUM_EDGES + 255) / 256, 256>>>(esrc, edst);
    prep_w<<<192, 256>>>(w_l, w_r, w_out);
    agg_half<<<(NUM_DST + 7) / 8, 256>>>(x, 0);
    agg_half<<<(NUM_DST + 7) / 8, 256>>>(x, 1);

    fused_tc<<<NRB2, 512, GF_SMEM>>>(b_l, ln1_g, ln1_b, b_out, ln2_g, ln2_b, out);
}

// round 13
// speedup vs baseline: 1.9505x; 1.2448x over previous
#include <cuda_runtime.h>
#include <cuda_fp16.h>
#include <math.h>
#include <stdint.h>

#define NUM_SRC   200000
#define NUM_DST   100000
#define NUM_EDGES 1600000
#define IN_DIM    128
#define HID       256
#define OUT_DIM   128
#define NRB2      782       // ceil(NUM_DST/128)
#define BUCKET_CAP 64

// ---------------------------------------------------------------------------
// Scratch (__device__ globals; no allocation allowed)
// ---------------------------------------------------------------------------
__device__ __align__(16) int      g_deg[NUM_DST];
__device__ __align__(16) int      g_bucket[(size_t)NUM_DST * BUCKET_CAP];
__device__ __align__(16) uint32_t g_af[(size_t)NUM_DST * 128];   // A=[mean|x] fp16x2, [row][kp]
__device__ __align__(16) uint32_t g_wh[256 * 128];               // W_cat fp16 hi [n][kp]
__device__ __align__(16) uint32_t g_wl[256 * 128];               // W_cat fp16 lo
__device__ __align__(16) uint32_t g_wohi[128 * 128];             // W_out fp16 hi [n][kp]
__device__ __align__(16) uint32_t g_wolo[128 * 128];             // W_out fp16 lo

// ---------------------------------------------------------------------------
// helpers
// ---------------------------------------------------------------------------
__device__ __forceinline__ uint32_t smem_u32(const void* p) {
    uint32_t a;
    asm("{ .reg .u64 t; cvta.to.shared.u64 t, %1; cvt.u32.u64 %0, t; }" : "=r"(a) : "l"(p));
    return a;
}
__device__ __forceinline__ uint32_t packh2(float a, float b) {
    __half2 h = __floats2half2_rn(a, b);
    return *(uint32_t*)&h;
}
__device__ __forceinline__ void splitw2(float a, float b, uint32_t& hi, uint32_t& lo) {
    __half h0 = __float2half_rn(a), h1 = __float2half_rn(b);
    __half l0 = __float2half_rn(a - __half2float(h0));
    __half l1 = __float2half_rn(b - __half2float(h1));
    __half2 H; H.x = h0; H.y = h1;
    __half2 L; L.x = l0; L.y = l1;
    hi = *(uint32_t*)&H; lo = *(uint32_t*)&L;
}
__device__ __forceinline__ float gelu_exact(float t) {
    return 0.5f * t * (1.0f + erff(t * 0.70710678118654752f));
}

#define MMAH(c, A0, A1, A2, A3, B0, B1)                                         \
    asm("mma.sync.aligned.m16n8k16.row.col.f32.f16.f16.f32 "                    \
        "{%0,%1,%2,%3},{%4,%5,%6,%7},{%8,%9},{%0,%1,%2,%3};"                    \
        : "+f"((c)[0]), "+f"((c)[1]), "+f"((c)[2]), "+f"((c)[3])                \
        : "r"(A0), "r"(A1), "r"(A2), "r"(A3), "r"(B0), "r"(B1))

#define LDSM4(R, addr)                                                          \
    asm volatile("ldmatrix.sync.aligned.m8n8.x4.shared.b16 {%0,%1,%2,%3}, [%4];"\
        : "=r"((R)[0]), "=r"((R)[1]), "=r"((R)[2]), "=r"((R)[3]) : "r"(addr))

#define CPA(dst, src, sz)                                                       \
    asm volatile("cp.async.ca.shared.global [%0], [%1], 16, %2;"                \
        :: "r"(dst), "l"(src), "r"(sz))
#define CPA16(dst, src)                                                         \
    asm volatile("cp.async.ca.shared.global [%0], [%1], 16;" :: "r"(dst), "l"(src))
#define CPCOMMIT() asm volatile("cp.async.commit_group;" ::: "memory")

// ---------------------------------------------------------------------------
__global__ void zero_deg() {
    int i = blockIdx.x * 256 + threadIdx.x;
    if (i < NUM_DST) g_deg[i] = 0;
}

__global__ void fill_kernel(const int* __restrict__ esrc,
                            const int* __restrict__ edst) {
    int e = blockIdx.x * 256 + threadIdx.x;
    if (e >= NUM_EDGES) return;
    int s = __ldg(esrc + e);
    int d = __ldg(edst + e);
    int pos = atomicAdd(&g_deg[d], 1);
    if (pos < BUCKET_CAP)
        g_bucket[(size_t)d * BUCKET_CAP + pos] = s;
}

// ---------------------------------------------------------------------------
// aggregate, column-split; emits fp16 A directly.
// ---------------------------------------------------------------------------
__global__ void agg_half(const float* __restrict__ x, int half) {
    int d    = blockIdx.x * 8 + (threadIdx.x >> 5);
    int lane = threadIdx.x & 31;
    if (d >= NUM_DST) return;

    int degT = g_deg[d];
    int deg  = min(degT, BUCKET_CAP);
    const int* lst = g_bucket + (size_t)d * BUCKET_CAP;
    const float2* x2 = (const float2*)x;
    int off = half * 32 + lane;

    float s0 = 0.f, s1 = 0.f;
    int i = 0;
    for (; i + 8 <= deg; i += 8) {
        int e0 = __ldg(lst + i),     e1 = __ldg(lst + i + 1);
        int e2 = __ldg(lst + i + 2), e3 = __ldg(lst + i + 3);
        int e4 = __ldg(lst + i + 4), e5 = __ldg(lst + i + 5);
        int e6 = __ldg(lst + i + 6), e7 = __ldg(lst + i + 7);
        float2 v0 = __ldg(x2 + (size_t)e0 * 64 + off);
        float2 v1 = __ldg(x2 + (size_t)e1 * 64 + off);
        float2 v2 = __ldg(x2 + (size_t)e2 * 64 + off);
        float2 v3 = __ldg(x2 + (size_t)e3 * 64 + off);
        float2 v4 = __ldg(x2 + (size_t)e4 * 64 + off);
        float2 v5 = __ldg(x2 + (size_t)e5 * 64 + off);
        float2 v6 = __ldg(x2 + (size_t)e6 * 64 + off);
        float2 v7 = __ldg(x2 + (size_t)e7 * 64 + off);
        s0 += v0.x + v1.x + v2.x + v3.x + v4.x + v5.x + v6.x + v7.x;
        s1 += v0.y + v1.y + v2.y + v3.y + v4.y + v5.y + v6.y + v7.y;
    }
    for (; i + 4 <= deg; i += 4) {
        int e0 = __ldg(lst + i),     e1 = __ldg(lst + i + 1);
        int e2 = __ldg(lst + i + 2), e3 = __ldg(lst + i + 3);
        float2 v0 = __ldg(x2 + (size_t)e0 * 64 + off);
        float2 v1 = __ldg(x2 + (size_t)e1 * 64 + off);
        float2 v2 = __ldg(x2 + (size_t)e2 * 64 + off);
        float2 v3 = __ldg(x2 + (size_t)e3 * 64 + off);
        s0 += v0.x + v1.x + v2.x + v3.x;
        s1 += v0.y + v1.y + v2.y + v3.y;
    }
    for (; i < deg; ++i) {
        int e = __ldg(lst + i);
        float2 v = __ldg(x2 + (size_t)e * 64 + off);
        s0 += v.x; s1 += v.y;
    }

    float inv = 1.0f / fmaxf((float)degT, 1.0f);
    g_af[(size_t)d * 128 + half * 32 + lane] = packh2(s0 * inv, s1 * inv);

    float2 xv = __ldg(x2 + (size_t)d * 64 + off);
    g_af[(size_t)d * 128 + 64 + half * 32 + lane] = packh2(xv.x, xv.y);
}

// ---------------------------------------------------------------------------
// prep_w — fp16 hi + fp16 residual, [n][kp] layout.
// ---------------------------------------------------------------------------
__global__ void prep_w(const float* __restrict__ w_l,
                       const float* __restrict__ w_r,
                       const float* __restrict__ w_out) {
    int t = blockIdx.x * 256 + threadIdx.x;
    if (t < 32768) {
        int kp = t >> 8, n = t & 255;
        int k0 = 2 * kp;
        float v0, v1;
        if (k0 < 128) { v0 = w_l[k0 * 256 + n];         v1 = w_l[(k0 + 1) * 256 + n]; }
        else          { v0 = w_r[(k0 - 128) * 256 + n]; v1 = w_r[(k0 - 127) * 256 + n]; }
        uint32_t hi, lo; splitw2(v0, v1, hi, lo);
        g_wh[n * 128 + kp] = hi; g_wl[n * 128 + kp] = lo;
    } else {
        int u = t - 32768;
        int kp = u >> 7, n = u & 127;
        int k0 = 2 * kp;
        float v0 = w_out[k0 * 128 + n], v1 = w_out[(k0 + 1) * 128 + n];
        uint32_t hi, lo; splitw2(v0, v1, hi, lo);
        g_wohi[n * 128 + kp] = hi; g_wolo[n * 128 + kp] = lo;
    }
}

// ---------------------------------------------------------------------------
// fused, M=128/CTA, fp16 2-term (A fp16, W = Wh + Wl).
// Phase 1: 128x256, 16 warps 4m x 4n (warp tile 32x64), K=256 in 4 chunks.
// Phase 2: 128x128 from smem h (fp16), W_out double-buffered.
// smem (bytes):
//   phase1 stage s @ s*81920: A 16K@0, Wh 32K@16384, Wl 32K@49152
//   phase2: h fp16 64K@0, Wout stage s @ 65536+s*32768 (hi 16K, lo 16K)
// Total 163840.
// ---------------------------------------------------------------------------
#define GF_SMEM 163840
__global__ __launch_bounds__(512, 1)
void fused_tc(const float* __restrict__ b_l,
              const float* __restrict__ ln1_g,
              const float* __restrict__ ln1_b,
              const float* __restrict__ b_out,
              const float* __restrict__ ln2_g,
              const float* __restrict__ ln2_b,
              float* __restrict__ out) {
    extern __shared__ uint32_t sm[];
    __shared__ float sSum[128][4], sSq[128][4];
    uint32_t sb = smem_u32(sm);

    int tid = threadIdx.x, wid = tid >> 5, lane = tid & 31;
    int wm = wid >> 2, wn = wid & 3;          // 4m x 4n
    int g = lane >> 2, t4 = lane & 3;
    int row0 = blockIdx.x * 128;

    float acc[2][8][4];
#pragma unroll
    for (int mt = 0; mt < 2; ++mt)
#pragma unroll
        for (int nt = 0; nt < 8; ++nt)
#pragma unroll
            for (int j = 0; j < 4; ++j) acc[mt][nt][j] = 0.f;

#define P1_ISSUE(kc, s) do {                                                      \
        uint32_t base = sb + (s) * 81920;                                         \
        for (int i = tid; i < 1024; i += 512) {                                   \
            int r_ = i >> 3, c_ = i & 7;                                          \
            int grow_ = row0 + r_;                                                \
            uint32_t sz_ = (grow_ < NUM_DST) ? 16u : 0u;                          \
            uint32_t d_ = base + (uint32_t)(r_ * 8 + (c_ ^ (r_ & 7))) * 16;       \
            CPA(d_, g_af + (size_t)grow_ * 128 + (kc) * 32 + c_ * 4, sz_);        \
        }                                                                         \
        for (int i = tid; i < 2048; i += 512) {                                   \
            int n_ = i >> 3, c_ = i & 7;                                          \
            uint32_t d_ = base + 16384 + (uint32_t)(n_ * 8 + (c_ ^ (n_ & 7))) * 16;\
            CPA16(d_, g_wh + n_ * 128 + (kc) * 32 + c_ * 4);                      \
            CPA16(d_ + 32768, g_wl + n_ * 128 + (kc) * 32 + c_ * 4);              \
        }                                                                         \
        CPCOMMIT();                                                               \
    } while (0)

#define WOUT_ISSUE(kc, s) do {                                                    \
        uint32_t b2 = sb + 65536 + (s) * 32768;                                   \
        for (int i = tid; i < 1024; i += 512) {                                   \
            int n_ = i >> 3, c_ = i & 7;                                          \
            uint32_t d_ = b2 + (uint32_t)(n_ * 8 + (c_ ^ (n_ & 7))) * 16;         \
            CPA16(d_, g_wohi + n_ * 128 + (kc) * 32 + c_ * 4);                    \
            CPA16(d_ + 16384, g_wolo + n_ * 128 + (kc) * 32 + c_ * 4);            \
        }                                                                         \
        CPCOMMIT();                                                               \
    } while (0)

    P1_ISSUE(0, 0);

    int arow = (lane & 15);
    int asel = lane >> 4;
    int wrow = ((lane >> 4) << 3) + (lane & 7);
    int wsel = (lane >> 3) & 1;

    // ================= Phase 1 mainloop =================
    for (int kc = 0; kc < 4; ++kc) {
        if (kc < 3) {
            P1_ISSUE(kc + 1, (kc + 1) & 1);
            asm volatile("cp.async.wait_group 1;" ::: "memory");
        } else {
            asm volatile("cp.async.wait_group 0;" ::: "memory");
        }
        __syncthreads();
        uint32_t base = sb + (kc & 1) * 81920;

#pragma unroll
        for (int ks = 0; ks < 4; ++ks) {
            uint32_t a_f[2][4];
#pragma unroll
            for (int mt = 0; mt < 2; ++mt) {
                int r = wm * 32 + mt * 16 + arow;
                uint32_t ad = base + (uint32_t)(r * 8 + ((2 * ks + asel) ^ (r & 7))) * 16;
                LDSM4(a_f[mt], ad);
            }
#pragma unroll
            for (int ntp = 0; ntp < 4; ++ntp) {
                uint32_t b_h[4], b_l2[4];
                int n_ = wn * 64 + ntp * 16 + wrow;
                uint32_t wd = base + 16384 + (uint32_t)(n_ * 8 + ((2 * ks + wsel) ^ (n_ & 7))) * 16;
                LDSM4(b_h, wd);
                LDSM4(b_l2, wd + 32768);
#pragma unroll
                for (int sub = 0; sub < 2; ++sub) {
                    int nt = ntp * 2 + sub;
                    uint32_t bh0 = b_h[sub * 2], bh1 = b_h[sub * 2 + 1];
                    uint32_t bl0 = b_l2[sub * 2], bl1 = b_l2[sub * 2 + 1];
#pragma unroll
                    for (int mt = 0; mt < 2; ++mt) {
                        MMAH(acc[mt][nt], a_f[mt][0], a_f[mt][1], a_f[mt][2], a_f[mt][3], bh0, bh1);
                        MMAH(acc[mt][nt], a_f[mt][0], a_f[mt][1], a_f[mt][2], a_f[mt][3], bl0, bl1);
                    }
                }
            }
        }
        __syncthreads();
    }

    WOUT_ISSUE(0, 0);

    // ================= Epilogue 1: bias + LN1 + GELU -> smem h (fp16) =================
#pragma unroll
    for (int nt = 0; nt < 8; ++nt) {
        int col = wn * 64 + nt * 8 + t4 * 2;
        float b0 = __ldg(b_l + col), b1 = __ldg(b_l + col + 1);
#pragma unroll
        for (int mt = 0; mt < 2; ++mt) {
            acc[mt][nt][0] += b0; acc[mt][nt][1] += b1;
            acc[mt][nt][2] += b0; acc[mt][nt][3] += b1;
        }
    }
#pragma unroll
    for (int mt = 0; mt < 2; ++mt)
#pragma unroll
        for (int ro = 0; ro < 2; ++ro) {
            float s = 0.f, q = 0.f;
#pragma unroll
            for (int nt = 0; nt < 8; ++nt) {
                float c0 = acc[mt][nt][ro * 2], c1 = acc[mt][nt][ro * 2 + 1];
                s += c0 + c1; q += c0 * c0 + c1 * c1;
            }
            s += __shfl_xor_sync(0xffffffffu, s, 1); q += __shfl_xor_sync(0xffffffffu, q, 1);
            s += __shfl_xor_sync(0xffffffffu, s, 2); q += __shfl_xor_sync(0xffffffffu, q, 2);
            if (t4 == 0) {
                int r = wm * 32 + mt * 16 + ro * 8 + g;
                sSum[r][wn] = s; sSq[r][wn] = q;
            }
        }
    __syncthreads();

#pragma unroll
    for (int mt = 0; mt < 2; ++mt)
#pragma unroll
        for (int ro = 0; ro < 2; ++ro) {
            int r = wm * 32 + mt * 16 + ro * 8 + g;
            float S = sSum[r][0] + sSum[r][1] + sSum[r][2] + sSum[r][3];
            float SQ = sSq[r][0] + sSq[r][1] + sSq[r][2] + sSq[r][3];
            float mu   = S * (1.0f / HID);
            float var  = SQ * (1.0f / HID) - mu * mu;
            float rstd = rsqrtf(var + 1e-5f);
#pragma unroll
            for (int nt = 0; nt < 8; ++nt) {
                int col = wn * 64 + nt * 8 + t4 * 2;
                float c0 = acc[mt][nt][ro * 2], c1 = acc[mt][nt][ro * 2 + 1];
                float v0 = gelu_exact((c0 - mu) * rstd * __ldg(ln1_g + col)     + __ldg(ln1_b + col));
                float v1 = gelu_exact((c1 - mu) * rstd * __ldg(ln1_g + col + 1) + __ldg(ln1_b + col + 1));
                int kp = col >> 1;
                uint32_t off = (uint32_t)(r * 32 + ((kp >> 2) ^ (r & 7))) * 16 + (kp & 3) * 4;
                *(uint32_t*)((char*)sm + off) = packh2(v0, v1);
            }
        }
    __syncthreads();

    // ================= Phase 2: out-gemm, A from smem h =================
    float acc2[2][4][4];
#pragma unroll
    for (int mt = 0; mt < 2; ++mt)
#pragma unroll
        for (int nt = 0; nt < 4; ++nt)
#pragma unroll
            for (int j = 0; j < 4; ++j) acc2[mt][nt][j] = 0.f;

    for (int kc = 0; kc < 4; ++kc) {
        if (kc < 3) {
            WOUT_ISSUE(kc + 1, (kc + 1) & 1);
            asm volatile("cp.async.wait_group 1;" ::: "memory");
        } else {
            asm volatile("cp.async.wait_group 0;" ::: "memory");
        }
        __syncthreads();
        uint32_t b2 = sb + 65536 + (kc & 1) * 32768;

#pragma unroll
        for (int ks = 0; ks < 4; ++ks) {
            uint32_t a_f[2][4];
#pragma unroll
            for (int mt = 0; mt < 2; ++mt) {
                int r = wm * 32 + mt * 16 + arow;
                uint32_t ad = sb + (uint32_t)(r * 32 + ((kc * 8 + 2 * ks + asel) ^ (r & 7))) * 16;
                LDSM4(a_f[mt], ad);
            }
#pragma unroll
            for (int ntp = 0; ntp < 2; ++ntp) {
                uint32_t b_h[4], b_l2[4];
                int n_ = wn * 32 + ntp * 16 + wrow;
                uint32_t wd = b2 + (uint32_t)(n_ * 8 + ((2 * ks + wsel) ^ (n_ & 7))) * 16;
                LDSM4(b_h, wd);
                LDSM4(b_l2, wd + 16384);
#pragma unroll
                for (int sub = 0; sub < 2; ++sub) {
                    int nt = ntp * 2 + sub;
                    uint32_t bh0 = b_h[sub * 2], bh1 = b_h[sub * 2 + 1];
                    uint32_t bl0 = b_l2[sub * 2], bl1 = b_l2[sub * 2 + 1];
#pragma unroll
                    for (int mt = 0; mt < 2; ++mt) {
                        MMAH(acc2[mt][nt], a_f[mt][0], a_f[mt][1], a_f[mt][2], a_f[mt][3], bh0, bh1);
                        MMAH(acc2[mt][nt], a_f[mt][0], a_f[mt][1], a_f[mt][2], a_f[mt][3], bl0, bl1);
                    }
                }
            }
        }
        __syncthreads();
    }

    // ================= Epilogue 2: bias + LN2 -> out =================
#pragma unroll
    for (int nt = 0; nt < 4; ++nt) {
        int col = wn * 32 + nt * 8 + t4 * 2;
        float b0 = __ldg(b_out + col), b1 = __ldg(b_out + col + 1);
#pragma unroll
        for (int mt = 0; mt < 2; ++mt) {
            acc2[mt][nt][0] += b0; acc2[mt][nt][1] += b1;
            acc2[mt][nt][2] += b0; acc2[mt][nt][3] += b1;
        }
    }
#pragma unroll
    for (int mt = 0; mt < 2; ++mt)
#pragma unroll
        for (int ro = 0; ro < 2; ++ro) {
            float s = 0.f, q = 0.f;
#pragma unroll
            for (int nt = 0; nt < 4; ++nt) {
                float c0 = acc2[mt][nt][ro * 2], c1 = acc2[mt][nt][ro * 2 + 1];
                s += c0 + c1; q += c0 * c0 + c1 * c1;
            }
            s += __shfl_xor_sync(0xffffffffu, s, 1); q += __shfl_xor_sync(0xffffffffu, q, 1);
            s += __shfl_xor_sync(0xffffffffu, s, 2); q += __shfl_xor_sync(0xffffffffu, q, 2);
            if (t4 == 0) {
                int r = wm * 32 + mt * 16 + ro * 8 + g;
                sSum[r][wn] = s; sSq[r][wn] = q;
            }
        }
    __syncthreads();

#pragma unroll
    for (int mt = 0; mt < 2; ++mt)
#pragma unroll
        for (int ro = 0; ro < 2; ++ro) {
            int r = wm * 32 + mt * 16 + ro * 8 + g;
            int grow = row0 + r;
            float S = sSum[r][0] + sSum[r][1] + sSum[r][2] + sSum[r][3];
            float SQ = sSq[r][0] + sSq[r][1] + sSq[r][2] + sSq[r][3];
            float mu   = S * (1.0f / OUT_DIM);
            float var  = SQ * (1.0f / OUT_DIM) - mu * mu;
            float rstd = rsqrtf(var + 1e-5f);
            if (grow >= NUM_DST) continue;
#pragma unroll
            for (int nt = 0; nt < 4; ++nt) {
                int col = wn * 32 + nt * 8 + t4 * 2;
                float c0 = acc2[mt][nt][ro * 2], c1 = acc2[mt][nt][ro * 2 + 1];
                float2 o;
                o.x = (c0 - mu) * rstd * __ldg(ln2_g + col)     + __ldg(ln2_b + col);
                o.y = (c1 - mu) * rstd * __ldg(ln2_g + col + 1) + __ldg(ln2_b + col + 1);
                *(float2*)(out + (size_t)grow * 128 + col) = o;
            }
        }
}

// ---------------------------------------------------------------------------
extern "C" void kernel_launch(void* const* d_in, const int* in_sizes, int n_in,
                              void* d_out, int out_size) {
    const float* x     = (const float*)d_in[0];
    const float* w_l   = (const float*)d_in[1];
    const float* b_l   = (const float*)d_in[2];
    const float* w_r   = (const float*)d_in[3];
    const float* ln1_g = (const float*)d_in[4];
    const float* ln1_b = (const float*)d_in[5];
    const float* w_out = (const float*)d_in[6];
    const float* b_out = (const float*)d_in[7];
    const float* ln2_g = (const float*)d_in[8];
    const float* ln2_b = (const float*)d_in[9];
    const int*   esrc  = (const int*)d_in[10];
    const int*   edst  = (const int*)d_in[11];
    float* out = (float*)d_out;

    cudaFuncSetAttribute(fused_tc, cudaFuncAttributeMaxDynamicSharedMemorySize, GF_SMEM);

    zero_deg<<<(NUM_DST + 255) / 256, 256>>>();
    fill_kernel<<<(NUM_EDGES + 255) / 256, 256>>>(esrc, edst);
    prep_w<<<192, 256>>>(w_l, w_r, w_out);
    agg_half<<<(NUM_DST + 7) / 8, 256>>>(x, 0);
    agg_half<<<(NUM_DST + 7) / 8, 256>>>(x, 1);

    fused_tc<<<NRB2, 512, GF_SMEM>>>(b_l, ln1_g, ln1_b, b_out, ln2_g, ln2_b, out);
}

// round 16
// speedup vs baseline: 2.3412x; 1.2003x over previous
#include <cuda_runtime.h>
#include <cuda_fp16.h>
#include <math.h>
#include <stdint.h>

#define NUM_SRC   200000
#define NUM_DST   100000
#define NUM_EDGES 1600000
#define IN_DIM    128
#define HID       256
#define OUT_DIM   128
#define NRB2      782       // ceil(NUM_DST/128)
#define BUCKET_CAP 64

// ---------------------------------------------------------------------------
// Scratch (__device__ globals; no allocation allowed)
// ---------------------------------------------------------------------------
__device__ __align__(16) int      g_deg[NUM_DST];
__device__ __align__(16) int      g_bucket[(size_t)NUM_DST * BUCKET_CAP];
__device__ __align__(16) uint32_t g_af[(size_t)NUM_DST * 128];   // A=[mean|x] fp16x2, [row][kp]
__device__ __align__(16) uint32_t g_wh[256 * 128];               // W_cat fp16 [n][kp]
__device__ __align__(16) uint32_t g_wohi[128 * 128];             // W_out fp16 [n][kp]

// ---------------------------------------------------------------------------
// helpers
// ---------------------------------------------------------------------------
__device__ __forceinline__ uint32_t smem_u32(const void* p) {
    uint32_t a;
    asm("{ .reg .u64 t; cvta.to.shared.u64 t, %1; cvt.u32.u64 %0, t; }" : "=r"(a) : "l"(p));
    return a;
}
__device__ __forceinline__ uint32_t packh2(float a, float b) {
    __half2 h = __floats2half2_rn(a, b);
    return *(uint32_t*)&h;
}
__device__ __forceinline__ float gelu_exact(float t) {
    return 0.5f * t * (1.0f + erff(t * 0.70710678118654752f));
}

#define MMAH(c, A0, A1, A2, A3, B0, B1)                                         \
    asm("mma.sync.aligned.m16n8k16.row.col.f32.f16.f16.f32 "                    \
        "{%0,%1,%2,%3},{%4,%5,%6,%7},{%8,%9},{%0,%1,%2,%3};"                    \
        : "+f"((c)[0]), "+f"((c)[1]), "+f"((c)[2]), "+f"((c)[3])                \
        : "r"(A0), "r"(A1), "r"(A2), "r"(A3), "r"(B0), "r"(B1))

#define LDSM4(R, addr)                                                          \
    asm volatile("ldmatrix.sync.aligned.m8n8.x4.shared.b16 {%0,%1,%2,%3}, [%4];"\
        : "=r"((R)[0]), "=r"((R)[1]), "=r"((R)[2]), "=r"((R)[3]) : "r"(addr))

#define CPA(dst, src, sz)                                                       \
    asm volatile("cp.async.ca.shared.global [%0], [%1], 16, %2;"                \
        :: "r"(dst), "l"(src), "r"(sz))
#define CPA16(dst, src)                                                         \
    asm volatile("cp.async.ca.shared.global [%0], [%1], 16;" :: "r"(dst), "l"(src))
#define CPCOMMIT() asm volatile("cp.async.commit_group;" ::: "memory")

// ---------------------------------------------------------------------------
__global__ void zero_deg() {
    int i = blockIdx.x * 256 + threadIdx.x;
    if (i < NUM_DST) g_deg[i] = 0;
}

__global__ void fill_kernel(const int* __restrict__ esrc,
                            const int* __restrict__ edst) {
    int e = blockIdx.x * 256 + threadIdx.x;
    if (e >= NUM_EDGES) return;
    int s = __ldg(esrc + e);
    int d = __ldg(edst + e);
    int pos = atomicAdd(&g_deg[d], 1);
    if (pos < BUCKET_CAP)
        g_bucket[(size_t)d * BUCKET_CAP + pos] = s;
}

// ---------------------------------------------------------------------------
// aggregate, column-split; emits fp16 A directly. (R13 winner, unchanged)
// ---------------------------------------------------------------------------
__global__ void agg_half(const float* __restrict__ x, int half) {
    int d    = blockIdx.x * 8 + (threadIdx.x >> 5);
    int lane = threadIdx.x & 31;
    if (d >= NUM_DST) return;

    int degT = g_deg[d];
    int deg  = min(degT, BUCKET_CAP);
    const int* lst = g_bucket + (size_t)d * BUCKET_CAP;
    const float2* x2 = (const float2*)x;
    int off = half * 32 + lane;

    float s0 = 0.f, s1 = 0.f;
    int i = 0;
    for (; i + 8 <= deg; i += 8) {
        int e0 = __ldg(lst + i),     e1 = __ldg(lst + i + 1);
        int e2 = __ldg(lst + i + 2), e3 = __ldg(lst + i + 3);
        int e4 = __ldg(lst + i + 4), e5 = __ldg(lst + i + 5);
        int e6 = __ldg(lst + i + 6), e7 = __ldg(lst + i + 7);
        float2 v0 = __ldg(x2 + (size_t)e0 * 64 + off);
        float2 v1 = __ldg(x2 + (size_t)e1 * 64 + off);
        float2 v2 = __ldg(x2 + (size_t)e2 * 64 + off);
        float2 v3 = __ldg(x2 + (size_t)e3 * 64 + off);
        float2 v4 = __ldg(x2 + (size_t)e4 * 64 + off);
        float2 v5 = __ldg(x2 + (size_t)e5 * 64 + off);
        float2 v6 = __ldg(x2 + (size_t)e6 * 64 + off);
        float2 v7 = __ldg(x2 + (size_t)e7 * 64 + off);
        s0 += v0.x + v1.x + v2.x + v3.x + v4.x + v5.x + v6.x + v7.x;
        s1 += v0.y + v1.y + v2.y + v3.y + v4.y + v5.y + v6.y + v7.y;
    }
    for (; i + 4 <= deg; i += 4) {
        int e0 = __ldg(lst + i),     e1 = __ldg(lst + i + 1);
        int e2 = __ldg(lst + i + 2), e3 = __ldg(lst + i + 3);
        float2 v0 = __ldg(x2 + (size_t)e0 * 64 + off);
        float2 v1 = __ldg(x2 + (size_t)e1 * 64 + off);
        float2 v2 = __ldg(x2 + (size_t)e2 * 64 + off);
        float2 v3 = __ldg(x2 + (size_t)e3 * 64 + off);
        s0 += v0.x + v1.x + v2.x + v3.x;
        s1 += v0.y + v1.y + v2.y + v3.y;
    }
    for (; i < deg; ++i) {
        int e = __ldg(lst + i);
        float2 v = __ldg(x2 + (size_t)e * 64 + off);
        s0 += v.x; s1 += v.y;
    }

    float inv = 1.0f / fmaxf((float)degT, 1.0f);
    g_af[(size_t)d * 128 + half * 32 + lane] = packh2(s0 * inv, s1 * inv);

    float2 xv = __ldg(x2 + (size_t)d * 64 + off);
    g_af[(size_t)d * 128 + 64 + half * 32 + lane] = packh2(xv.x, xv.y);
}

// ---------------------------------------------------------------------------
// prep_w — single fp16, [n][kp] layout.
// ---------------------------------------------------------------------------
__global__ void prep_w(const float* __restrict__ w_l,
                       const float* __restrict__ w_r,
                       const float* __restrict__ w_out) {
    int t = blockIdx.x * 256 + threadIdx.x;
    if (t < 32768) {
        int kp = t >> 8, n = t & 255;
        int k0 = 2 * kp;
        float v0, v1;
        if (k0 < 128) { v0 = w_l[k0 * 256 + n];         v1 = w_l[(k0 + 1) * 256 + n]; }
        else          { v0 = w_r[(k0 - 128) * 256 + n]; v1 = w_r[(k0 - 127) * 256 + n]; }
        g_wh[n * 128 + kp] = packh2(v0, v1);
    } else {
        int u = t - 32768;
        int kp = u >> 7, n = u & 127;
        int k0 = 2 * kp;
        g_wohi[n * 128 + kp] = packh2(w_out[k0 * 128 + n], w_out[(k0 + 1) * 128 + n]);
    }
}

// ---------------------------------------------------------------------------
// fused, M=128/CTA, pure fp16 single-term.
// Phase 1: 128x256, 16 warps 4m x 4n (warp tile 32x64), K=256 in 4 chunks.
// Phase 2: 128x128 from smem h (fp16), W_out double-buffered.
// smem (bytes):
//   phase1 stage s @ s*49152: A 16K@0, W 32K@16384          (2 stages = 96K)
//   phase2: h fp16 64K@0, Wout stage s @ 65536+s*16384      (total 96K)
// GF_SMEM = 98304.
// ---------------------------------------------------------------------------
#define GF_SMEM 98304
__global__ __launch_bounds__(512, 1)
void fused_tc(const float* __restrict__ b_l,
              const float* __restrict__ ln1_g,
              const float* __restrict__ ln1_b,
              const float* __restrict__ b_out,
              const float* __restrict__ ln2_g,
              const float* __restrict__ ln2_b,
              float* __restrict__ out) {
    extern __shared__ uint32_t sm[];
    __shared__ float sSum[128][4], sSq[128][4];
    uint32_t sb = smem_u32(sm);

    int tid = threadIdx.x, wid = tid >> 5, lane = tid & 31;
    int wm = wid >> 2, wn = wid & 3;          // 4m x 4n
    int g = lane >> 2, t4 = lane & 3;
    int row0 = blockIdx.x * 128;

    float acc[2][8][4];
#pragma unroll
    for (int mt = 0; mt < 2; ++mt)
#pragma unroll
        for (int nt = 0; nt < 8; ++nt)
#pragma unroll
            for (int j = 0; j < 4; ++j) acc[mt][nt][j] = 0.f;

#define P1_ISSUE(kc, s) do {                                                      \
        uint32_t base = sb + (s) * 49152;                                         \
        for (int i = tid; i < 1024; i += 512) {                                   \
            int r_ = i >> 3, c_ = i & 7;                                          \
            int grow_ = row0 + r_;                                                \
            uint32_t sz_ = (grow_ < NUM_DST) ? 16u : 0u;                          \
            uint32_t d_ = base + (uint32_t)(r_ * 8 + (c_ ^ (r_ & 7))) * 16;       \
            CPA(d_, g_af + (size_t)grow_ * 128 + (kc) * 32 + c_ * 4, sz_);        \
        }                                                                         \
        for (int i = tid; i < 2048; i += 512) {                                   \
            int n_ = i >> 3, c_ = i & 7;                                          \
            uint32_t d_ = base + 16384 + (uint32_t)(n_ * 8 + (c_ ^ (n_ & 7))) * 16;\
            CPA16(d_, g_wh + n_ * 128 + (kc) * 32 + c_ * 4);                      \
        }                                                                         \
        CPCOMMIT();                                                               \
    } while (0)

#define WOUT_ISSUE(kc, s) do {                                                    \
        uint32_t b2 = sb + 65536 + (s) * 16384;                                   \
        for (int i = tid; i < 1024; i += 512) {                                   \
            int n_ = i >> 3, c_ = i & 7;                                          \
            uint32_t d_ = b2 + (uint32_t)(n_ * 8 + (c_ ^ (n_ & 7))) * 16;         \
            CPA16(d_, g_wohi + n_ * 128 + (kc) * 32 + c_ * 4);                    \
        }                                                                         \
        CPCOMMIT();                                                               \
    } while (0)

    P1_ISSUE(0, 0);

    int arow = (lane & 15);
    int asel = lane >> 4;
    int wrow = ((lane >> 4) << 3) + (lane & 7);
    int wsel = (lane >> 3) & 1;

    // ================= Phase 1 mainloop =================
    for (int kc = 0; kc < 4; ++kc) {
        if (kc < 3) {
            P1_ISSUE(kc + 1, (kc + 1) & 1);
            asm volatile("cp.async.wait_group 1;" ::: "memory");
        } else {
            asm volatile("cp.async.wait_group 0;" ::: "memory");
        }
        __syncthreads();
        uint32_t base = sb + (kc & 1) * 49152;

#pragma unroll
        for (int ks = 0; ks < 4; ++ks) {
            uint32_t a_f[2][4];
#pragma unroll
            for (int mt = 0; mt < 2; ++mt) {
                int r = wm * 32 + mt * 16 + arow;
                uint32_t ad = base + (uint32_t)(r * 8 + ((2 * ks + asel) ^ (r & 7))) * 16;
                LDSM4(a_f[mt], ad);
            }
#pragma unroll
            for (int ntp = 0; ntp < 4; ++ntp) {
                uint32_t b_h[4];
                int n_ = wn * 64 + ntp * 16 + wrow;
                uint32_t wd = base + 16384 + (uint32_t)(n_ * 8 + ((2 * ks + wsel) ^ (n_ & 7))) * 16;
                LDSM4(b_h, wd);
#pragma unroll
                for (int sub = 0; sub < 2; ++sub) {
                    int nt = ntp * 2 + sub;
                    uint32_t bh0 = b_h[sub * 2], bh1 = b_h[sub * 2 + 1];
#pragma unroll
                    for (int mt = 0; mt < 2; ++mt)
                        MMAH(acc[mt][nt], a_f[mt][0], a_f[mt][1], a_f[mt][2], a_f[mt][3], bh0, bh1);
                }
            }
        }
        __syncthreads();
    }

    WOUT_ISSUE(0, 0);

    // ================= Epilogue 1: bias + LN1 + GELU -> smem h (fp16) =================
#pragma unroll
    for (int nt = 0; nt < 8; ++nt) {
        int col = wn * 64 + nt * 8 + t4 * 2;
        float b0 = __ldg(b_l + col), b1 = __ldg(b_l + col + 1);
#pragma unroll
        for (int mt = 0; mt < 2; ++mt) {
            acc[mt][nt][0] += b0; acc[mt][nt][1] += b1;
            acc[mt][nt][2] += b0; acc[mt][nt][3] += b1;
        }
    }
#pragma unroll
    for (int mt = 0; mt < 2; ++mt)
#pragma unroll
        for (int ro = 0; ro < 2; ++ro) {
            float s = 0.f, q = 0.f;
#pragma unroll
            for (int nt = 0; nt < 8; ++nt) {
                float c0 = acc[mt][nt][ro * 2], c1 = acc[mt][nt][ro * 2 + 1];
                s += c0 + c1; q += c0 * c0 + c1 * c1;
            }
            s += __shfl_xor_sync(0xffffffffu, s, 1); q += __shfl_xor_sync(0xffffffffu, q, 1);
            s += __shfl_xor_sync(0xffffffffu, s, 2); q += __shfl_xor_sync(0xffffffffu, q, 2);
            if (t4 == 0) {
                int r = wm * 32 + mt * 16 + ro * 8 + g;
                sSum[r][wn] = s; sSq[r][wn] = q;
            }
        }
    __syncthreads();

#pragma unroll
    for (int mt = 0; mt < 2; ++mt)
#pragma unroll
        for (int ro = 0; ro < 2; ++ro) {
            int r = wm * 32 + mt * 16 + ro * 8 + g;
            float S = sSum[r][0] + sSum[r][1] + sSum[r][2] + sSum[r][3];
            float SQ = sSq[r][0] + sSq[r][1] + sSq[r][2] + sSq[r][3];
            float mu   = S * (1.0f / HID);
            float var  = SQ * (1.0f / HID) - mu * mu;
            float rstd = rsqrtf(var + 1e-5f);
#pragma unroll
            for (int nt = 0; nt < 8; ++nt) {
                int col = wn * 64 + nt * 8 + t4 * 2;
                float c0 = acc[mt][nt][ro * 2], c1 = acc[mt][nt][ro * 2 + 1];
                float v0 = gelu_exact((c0 - mu) * rstd * __ldg(ln1_g + col)     + __ldg(ln1_b + col));
                float v1 = gelu_exact((c1 - mu) * rstd * __ldg(ln1_g + col + 1) + __ldg(ln1_b + col + 1));
                int kp = col >> 1;
                uint32_t off = (uint32_t)(r * 32 + ((kp >> 2) ^ (r & 7))) * 16 + (kp & 3) * 4;
                *(uint32_t*)((char*)sm + off) = packh2(v0, v1);
            }
        }
    __syncthreads();

    // ================= Phase 2: out-gemm, A from smem h =================
    float acc2[2][4][4];
#pragma unroll
    for (int mt = 0; mt < 2; ++mt)
#pragma unroll
        for (int nt = 0; nt < 4; ++nt)
#pragma unroll
            for (int j = 0; j < 4; ++j) acc2[mt][nt][j] = 0.f;

    for (int kc = 0; kc < 4; ++kc) {
        if (kc < 3) {
            WOUT_ISSUE(kc + 1, (kc + 1) & 1);
            asm volatile("cp.async.wait_group 1;" ::: "memory");
        } else {
            asm volatile("cp.async.wait_group 0;" ::: "memory");
        }
        __syncthreads();
        uint32_t b2 = sb + 65536 + (kc & 1) * 16384;

#pragma unroll
        for (int ks = 0; ks < 4; ++ks) {
            uint32_t a_f[2][4];
#pragma unroll
            for (int mt = 0; mt < 2; ++mt) {
                int r = wm * 32 + mt * 16 + arow;
                uint32_t ad = sb + (uint32_t)(r * 32 + ((kc * 8 + 2 * ks + asel) ^ (r & 7))) * 16;
                LDSM4(a_f[mt], ad);
            }
#pragma unroll
            for (int ntp = 0; ntp < 2; ++ntp) {
                uint32_t b_h[4];
                int n_ = wn * 32 + ntp * 16 + wrow;
                uint32_t wd = b2 + (uint32_t)(n_ * 8 + ((2 * ks + wsel) ^ (n_ & 7))) * 16;
                LDSM4(b_h, wd);
#pragma unroll
                for (int sub = 0; sub < 2; ++sub) {
                    int nt = ntp * 2 + sub;
                    uint32_t bh0 = b_h[sub * 2], bh1 = b_h[sub * 2 + 1];
#pragma unroll
                    for (int mt = 0; mt < 2; ++mt)
                        MMAH(acc2[mt][nt], a_f[mt][0], a_f[mt][1], a_f[mt][2], a_f[mt][3], bh0, bh1);
                }
            }
        }
        __syncthreads();
    }

    // ================= Epilogue 2: bias + LN2 -> out =================
#pragma unroll
    for (int nt = 0; nt < 4; ++nt) {
        int col = wn * 32 + nt * 8 + t4 * 2;
        float b0 = __ldg(b_out + col), b1 = __ldg(b_out + col + 1);
#pragma unroll
        for (int mt = 0; mt < 2; ++mt) {
            acc2[mt][nt][0] += b0; acc2[mt][nt][1] += b1;
            acc2[mt][nt][2] += b0; acc2[mt][nt][3] += b1;
        }
    }
#pragma unroll
    for (int mt = 0; mt < 2; ++mt)
#pragma unroll
        for (int ro = 0; ro < 2; ++ro) {
            float s = 0.f, q = 0.f;
#pragma unroll
            for (int nt = 0; nt < 4; ++nt) {
                float c0 = acc2[mt][nt][ro * 2], c1 = acc2[mt][nt][ro * 2 + 1];
                s += c0 + c1; q += c0 * c0 + c1 * c1;
            }
            s += __shfl_xor_sync(0xffffffffu, s, 1); q += __shfl_xor_sync(0xffffffffu, q, 1);
            s += __shfl_xor_sync(0xffffffffu, s, 2); q += __shfl_xor_sync(0xffffffffu, q, 2);
            if (t4 == 0) {
                int r = wm * 32 + mt * 16 + ro * 8 + g;
                sSum[r][wn] = s; sSq[r][wn] = q;
            }
        }
    __syncthreads();

#pragma unroll
    for (int mt = 0; mt < 2; ++mt)
#pragma unroll
        for (int ro = 0; ro < 2; ++ro) {
            int r = wm * 32 + mt * 16 + ro * 8 + g;
            int grow = row0 + r;
            float S = sSum[r][0] + sSum[r][1] + sSum[r][2] + sSum[r][3];
            float SQ = sSq[r][0] + sSq[r][1] + sSq[r][2] + sSq[r][3];
            float mu   = S * (1.0f / OUT_DIM);
            float var  = SQ * (1.0f / OUT_DIM) - mu * mu;
            float rstd = rsqrtf(var + 1e-5f);
            if (grow >= NUM_DST) continue;
#pragma unroll
            for (int nt = 0; nt < 4; ++nt) {
                int col = wn * 32 + nt * 8 + t4 * 2;
                float c0 = acc2[mt][nt][ro * 2], c1 = acc2[mt][nt][ro * 2 + 1];
                float2 o;
                o.x = (c0 - mu) * rstd * __ldg(ln2_g + col)     + __ldg(ln2_b + col);
                o.y = (c1 - mu) * rstd * __ldg(ln2_g + col + 1) + __ldg(ln2_b + col + 1);
                *(float2*)(out + (size_t)grow * 128 + col) = o;
            }
        }
}

// ---------------------------------------------------------------------------
extern "C" void kernel_launch(void* const* d_in, const int* in_sizes, int n_in,
                              void* d_out, int out_size) {
    const float* x     = (const float*)d_in[0];
    const float* w_l   = (const float*)d_in[1];
    const float* b_l   = (const float*)d_in[2];
    const float* w_r   = (const float*)d_in[3];
    const float* ln1_g = (const float*)d_in[4];
    const float* ln1_b = (const float*)d_in[5];
    const float* w_out = (const float*)d_in[6];
    const float* b_out = (const float*)d_in[7];
    const float* ln2_g = (const float*)d_in[8];
    const float* ln2_b = (const float*)d_in[9];
    const int*   esrc  = (const int*)d_in[10];
    const int*   edst  = (const int*)d_in[11];
    float* out = (float*)d_out;

    cudaFuncSetAttribute(fused_tc, cudaFuncAttributeMaxDynamicSharedMemorySize, GF_SMEM);

    zero_deg<<<(NUM_DST + 255) / 256, 256>>>();
    fill_kernel<<<(NUM_EDGES + 255) / 256, 256>>>(esrc, edst);
    prep_w<<<192, 256>>>(w_l, w_r, w_out);
    agg_half<<<(NUM_DST + 7) / 8, 256>>>(x, 0);
    agg_half<<<(NUM_DST + 7) / 8, 256>>>(x, 1);

    fused_tc<<<NRB2, 512, GF_SMEM>>>(b_l, ln1_g, ln1_b, b_out, ln2_g, ln2_b, out);
}